// round 1
// baseline (speedup 1.0000x reference)
#include <cuda_runtime.h>

#define NN 50000
#define EE 800000
#define FIN 500
#define HH 96

// ---------------- scratch (device globals; no allocation allowed) ----------
__device__ float g_norm_out[NN];
__device__ float g_norm_in[NN];
__device__ int   g_deg_out[NN];
__device__ int   g_deg_in[NN];
__device__ int   g_off[NN + 1];
__device__ int   g_cur[NN];
__device__ int   g_csr[EE];
__device__ float g_Y [NN * HH];   // x @ W1 (shared by both views)
__device__ float g_B0[NN * HH];
__device__ float g_B1[NN * HH];
__device__ float g_B2[NN * HH];
__device__ float g_wmsum[HH];
__device__ float g_bmsum;

// ---------------- degree / norm / CSR build --------------------------------
__global__ void k_zero_deg() {
    int i = blockIdx.x * blockDim.x + threadIdx.x;
    if (i < NN) { g_deg_out[i] = 0; g_deg_in[i] = 0; }
}

__global__ void k_count(const int* __restrict__ src, const int* __restrict__ dst) {
    int e = blockIdx.x * blockDim.x + threadIdx.x;
    if (e < EE) {
        atomicAdd(&g_deg_out[src[e]], 1);
        atomicAdd(&g_deg_in[dst[e]], 1);
    }
}

__global__ void k_norm() {
    int i = blockIdx.x * blockDim.x + threadIdx.x;
    if (i < NN) {
        g_norm_out[i] = rsqrtf((float)max(g_deg_out[i], 1));
        g_norm_in[i]  = rsqrtf((float)max(g_deg_in[i], 1));
    }
}

// single-block exclusive scan of g_deg_in -> g_off, copy into g_cur
__global__ void k_scan() {
    const int T  = 1024;
    const int CH = (NN + T - 1) / T;  // 49
    int t = threadIdx.x;
    int b = t * CH;
    int e = min(b + CH, NN);

    int s = 0;
    for (int i = b; i < e; i++) s += g_deg_in[i];

    int lane = t & 31, wid = t >> 5;
    int inc = s;
    #pragma unroll
    for (int o = 1; o < 32; o <<= 1) {
        int u = __shfl_up_sync(0xffffffffu, inc, o);
        if (lane >= o) inc += u;
    }
    __shared__ int wsum[32];
    if (lane == 31) wsum[wid] = inc;
    __syncthreads();
    if (wid == 0) {
        int w = wsum[lane];
        #pragma unroll
        for (int o = 1; o < 32; o <<= 1) {
            int u = __shfl_up_sync(0xffffffffu, w, o);
            if (lane >= o) w += u;
        }
        wsum[lane] = w;
    }
    __syncthreads();
    int run = inc - s + (wid ? wsum[wid - 1] : 0);

    for (int i = b; i < e; i++) {
        g_off[i] = run;
        g_cur[i] = run;
        run += g_deg_in[i];
    }
    if (b < NN && e == NN) g_off[NN] = run;
}

__global__ void k_scatter(const int* __restrict__ src, const int* __restrict__ dst) {
    int e = blockIdx.x * blockDim.x + threadIdx.x;
    if (e < EE) {
        int p = atomicAdd(&g_cur[dst[e]], 1);
        g_csr[p] = src[e];
    }
}

// wmsum[k] = sum_j Wm[k,j];  bmsum = sum_j bm[j]
__global__ void k_wmsum(const float* __restrict__ Wm, const float* __restrict__ bm) {
    int k = threadIdx.x;
    if (k < HH) {
        float s = 0.f;
        for (int j = 0; j < HH; j++) s += Wm[k * HH + j];
        g_wmsum[k] = s;
    }
    if (k == 0) {
        float s = 0.f;
        for (int j = 0; j < HH; j++) s += bm[j];
        g_bmsum = s;
    }
}

// ---------------- GEMM: C[N,96] = A[N,KTOT] @ W[KTOT,96] -------------------
// 64 rows per block, 256 threads; thread = (32 col-groups x 8 row-groups),
// 8 rows x 3 cols per thread. xs reads are warp-broadcast; ws reads stride-1.
template <int KTOT, int KC, int LDA>
__global__ void k_gemm(const float* __restrict__ A, const float* __restrict__ W,
                       float* __restrict__ C) {
    __shared__ float xs[64][KC];
    __shared__ float ws[KC][HH];
    int r0  = blockIdx.x * 64;
    int tid = threadIdx.x;
    int tx = tid & 31, ty = tid >> 5;

    float acc[8][3];
    #pragma unroll
    for (int r = 0; r < 8; r++) { acc[r][0] = acc[r][1] = acc[r][2] = 0.f; }

    for (int kc = 0; kc < KTOT; kc += KC) {
        for (int idx = tid; idx < 64 * KC; idx += 256) {
            int r = idx / KC, k = idx - r * KC;
            int gr = r0 + r;
            xs[r][k] = (gr < NN) ? A[(size_t)gr * LDA + kc + k] : 0.f;
        }
        for (int idx = tid; idx < KC * HH; idx += 256) {
            int k = idx / HH, j = idx - k * HH;
            ws[k][j] = W[(size_t)(kc + k) * HH + j];
        }
        __syncthreads();
        #pragma unroll 2
        for (int k = 0; k < KC; k++) {
            float w0 = ws[k][tx], w1 = ws[k][tx + 32], w2 = ws[k][tx + 64];
            #pragma unroll
            for (int r = 0; r < 8; r++) {
                float xv = xs[ty * 8 + r][k];
                acc[r][0] = fmaf(xv, w0, acc[r][0]);
                acc[r][1] = fmaf(xv, w1, acc[r][1]);
                acc[r][2] = fmaf(xv, w2, acc[r][2]);
            }
        }
        __syncthreads();
    }
    #pragma unroll
    for (int r = 0; r < 8; r++) {
        int gr = r0 + ty * 8 + r;
        if (gr < NN) {
            float* o = C + (size_t)gr * HH;
            o[tx] = acc[r][0]; o[tx + 32] = acc[r][1]; o[tx + 64] = acc[r][2];
        }
    }
}

// ---------------- per-view elementwise stages ------------------------------
// B0[i,:] = norm_out[i] * Y[r(i),:]   (layer-1 pre-aggregation features)
__global__ void k_prescale(const int* __restrict__ perm, int use_perm) {
    int idx = blockIdx.x * blockDim.x + threadIdx.x;
    if (idx < NN * HH) {
        int i = idx / HH, j = idx - i * HH;
        int r = use_perm ? perm[i] : i;
        g_B0[idx] = g_norm_out[i] * g_Y[(size_t)r * HH + j];
    }
}

// SpMM gather: out[i,:] = sum_{e: dst=i} in[src_e,:]  (no atomics, no zeroing)
__global__ void k_spmm(const float* __restrict__ in, float* __restrict__ out) {
    int warp = (blockIdx.x * blockDim.x + threadIdx.x) >> 5;
    if (warp >= NN) return;
    int lane = threadIdx.x & 31;
    int b = g_off[warp], e = g_off[warp + 1];
    float a0 = 0.f, a1 = 0.f, a2 = 0.f;
    for (int p = b; p < e; p++) {
        const float* row = in + (size_t)g_csr[p] * HH;
        a0 += __ldg(row + lane);
        a1 += __ldg(row + lane + 32);
        a2 += __ldg(row + lane + 64);
    }
    float* o = out + (size_t)warp * HH;
    o[lane] = a0; o[lane + 32] = a1; o[lane + 64] = a2;
}

// B0[i,j] = norm_out[i] * prelu(B1[i,j]*norm_in[i] + b1[j], a1[j])
// (norm_out folded in as next layer's pre-scale)
__global__ void k_post1(const float* __restrict__ b1, const float* __restrict__ a1) {
    int idx = blockIdx.x * blockDim.x + threadIdx.x;
    if (idx < NN * HH) {
        int i = idx / HH, j = idx - i * HH;
        float h = g_B1[idx] * g_norm_in[i] + b1[j];
        h = (h >= 0.f) ? h : a1[j] * h;
        g_B0[idx] = g_norm_out[i] * h;
    }
}

// out[i] = bmsum + sum_j wmsum[j] * prelu(B1[i,j]*norm_in[i] + b2[j], a2[j])
__global__ void k_final(const float* __restrict__ b2, const float* __restrict__ a2,
                        float* __restrict__ out) {
    int warp = (blockIdx.x * blockDim.x + threadIdx.x) >> 5;
    if (warp >= NN) return;
    int lane = threadIdx.x & 31;
    float nin = g_norm_in[warp];
    float s = 0.f;
    #pragma unroll
    for (int c = 0; c < 3; c++) {
        int j = lane + c * 32;
        float h = g_B1[(size_t)warp * HH + j] * nin + b2[j];
        h = (h >= 0.f) ? h : a2[j] * h;
        s += h * g_wmsum[j];
    }
    #pragma unroll
    for (int o = 16; o; o >>= 1) s += __shfl_down_sync(0xffffffffu, s, o);
    if (lane == 0) out[warp] = s + g_bmsum;
}

// ---------------- launch ----------------------------------------------------
extern "C" void kernel_launch(void* const* d_in, const int* in_sizes, int n_in,
                              void* d_out, int out_size) {
    const float* x    = (const float*)d_in[0];
    const int*   src  = (const int*)  d_in[1];
    const int*   dst  = (const int*)  d_in[2];
    const int*   perm = (const int*)  d_in[3];
    const float* W1   = (const float*)d_in[4];
    const float* b1   = (const float*)d_in[5];
    const float* a1   = (const float*)d_in[6];
    const float* W2   = (const float*)d_in[7];
    const float* b2   = (const float*)d_in[8];
    const float* a2   = (const float*)d_in[9];
    const float* Wm   = (const float*)d_in[10];
    const float* bm   = (const float*)d_in[11];
    float* out = (float*)d_out;

    float *pY = nullptr, *pB0 = nullptr, *pB1 = nullptr, *pB2 = nullptr;
    cudaGetSymbolAddress((void**)&pY,  g_Y);
    cudaGetSymbolAddress((void**)&pB0, g_B0);
    cudaGetSymbolAddress((void**)&pB1, g_B1);
    cudaGetSymbolAddress((void**)&pB2, g_B2);

    const int GN  = (NN + 255) / 256;
    const int GE  = (EE + 255) / 256;
    const int GNH = (NN * HH + 255) / 256;
    const int GW  = (NN * 32 + 255) / 256;   // warp-per-node kernels
    const int GG  = (NN + 63) / 64;          // GEMM blocks

    k_zero_deg<<<GN, 256>>>();
    k_count<<<GE, 256>>>(src, dst);
    k_scan<<<1, 1024>>>();
    k_norm<<<GN, 256>>>();
    k_scatter<<<GE, 256>>>(src, dst);
    k_wmsum<<<1, 128>>>(Wm, bm);

    // Y = x @ W1 once, shared by both views
    k_gemm<FIN, 50, FIN><<<GG, 256>>>(x, W1, pY);

    for (int v = 0; v < 2; v++) {
        k_prescale<<<GNH, 256>>>(perm, v);
        k_spmm<<<GW, 256>>>(pB0, pB1);
        k_post1<<<GNH, 256>>>(b1, a1);
        k_gemm<HH, 48, HH><<<GG, 256>>>(pB0, W2, pB2);
        k_spmm<<<GW, 256>>>(pB2, pB1);
        k_final<<<GW, 256>>>(b2, a2, out + (size_t)v * NN);
    }
}

// round 3
// speedup vs baseline: 1.3644x; 1.3644x over previous
#include <cuda_runtime.h>
#include <cuda_bf16.h>
#include <cstdint>

#define NN 50000
#define EE 800000
#define FIN 500
#define HH 96

// ---------------- scratch (device globals; no allocation allowed) ----------
__device__ float g_norm_out[NN];
__device__ float g_norm_in[NN];
__device__ int   g_deg_out[NN];
__device__ int   g_deg_in[NN];
__device__ int   g_off[NN + 1];
__device__ int   g_cur[NN];
__device__ int   g_csr[EE];
__device__ float g_Y [NN * HH];   // x @ W1 (shared by both views)
__device__ float g_B0[NN * HH];
__device__ float g_B1[NN * HH];
__device__ float g_B2[NN * HH];
__device__ float g_wmsum[HH];
__device__ float g_bmsum;
// transposed (n-major, k-contiguous), zero-padded, bf16 hi/lo weight copies
__device__ __nv_bfloat16 g_W1t_h[HH * 512];
__device__ __nv_bfloat16 g_W1t_l[HH * 512];
__device__ __nv_bfloat16 g_W2t_h[HH * 128];
__device__ __nv_bfloat16 g_W2t_l[HH * 128];

// ---------------- helpers ----------------------------------------------------
__device__ __forceinline__ uint32_t pack_bf16(float x, float y) {
    __nv_bfloat162 t;
    t.x = __float2bfloat16_rn(x);
    t.y = __float2bfloat16_rn(y);
    return *reinterpret_cast<uint32_t*>(&t);
}

__device__ __forceinline__ void mma16816(float* c, uint32_t a0, uint32_t a1,
                                         uint32_t a2, uint32_t a3,
                                         uint32_t b0, uint32_t b1) {
    asm volatile(
        "mma.sync.aligned.m16n8k16.row.col.f32.bf16.bf16.f32 "
        "{%0,%1,%2,%3}, {%4,%5,%6,%7}, {%8,%9}, {%0,%1,%2,%3};"
        : "+f"(c[0]), "+f"(c[1]), "+f"(c[2]), "+f"(c[3])
        : "r"(a0), "r"(a1), "r"(a2), "r"(a3), "r"(b0), "r"(b1));
}

// ---------------- degree / norm / CSR build --------------------------------
__global__ void k_zero_deg() {
    int i = blockIdx.x * blockDim.x + threadIdx.x;
    if (i < NN) { g_deg_out[i] = 0; g_deg_in[i] = 0; }
}

__global__ void k_count(const int* __restrict__ src, const int* __restrict__ dst) {
    int e = blockIdx.x * blockDim.x + threadIdx.x;
    if (e < EE) {
        atomicAdd(&g_deg_out[src[e]], 1);
        atomicAdd(&g_deg_in[dst[e]], 1);
    }
}

__global__ void k_norm() {
    int i = blockIdx.x * blockDim.x + threadIdx.x;
    if (i < NN) {
        g_norm_out[i] = rsqrtf((float)max(g_deg_out[i], 1));
        g_norm_in[i]  = rsqrtf((float)max(g_deg_in[i], 1));
    }
}

__global__ void k_scan() {
    const int T  = 1024;
    const int CH = (NN + T - 1) / T;
    int t = threadIdx.x;
    int b = t * CH;
    int e = min(b + CH, NN);

    int s = 0;
    for (int i = b; i < e; i++) s += g_deg_in[i];

    int lane = t & 31, wid = t >> 5;
    int inc = s;
    #pragma unroll
    for (int o = 1; o < 32; o <<= 1) {
        int u = __shfl_up_sync(0xffffffffu, inc, o);
        if (lane >= o) inc += u;
    }
    __shared__ int wsum[32];
    if (lane == 31) wsum[wid] = inc;
    __syncthreads();
    if (wid == 0) {
        int w = wsum[lane];
        #pragma unroll
        for (int o = 1; o < 32; o <<= 1) {
            int u = __shfl_up_sync(0xffffffffu, w, o);
            if (lane >= o) w += u;
        }
        wsum[lane] = w;
    }
    __syncthreads();
    int run = inc - s + (wid ? wsum[wid - 1] : 0);

    for (int i = b; i < e; i++) {
        g_off[i] = run;
        g_cur[i] = run;
        run += g_deg_in[i];
    }
    if (b < NN && e == NN) g_off[NN] = run;
}

__global__ void k_scatter(const int* __restrict__ src, const int* __restrict__ dst) {
    int e = blockIdx.x * blockDim.x + threadIdx.x;
    if (e < EE) {
        int p = atomicAdd(&g_cur[dst[e]], 1);
        g_csr[p] = src[e];
    }
}

__global__ void k_wmsum(const float* __restrict__ Wm, const float* __restrict__ bm) {
    int k = threadIdx.x;
    if (k < HH) {
        float s = 0.f;
        for (int j = 0; j < HH; j++) s += Wm[k * HH + j];
        g_wmsum[k] = s;
    }
    if (k == 0) {
        float s = 0.f;
        for (int j = 0; j < HH; j++) s += bm[j];
        g_bmsum = s;
    }
}

// Wt[j][k] = W[k][j], zero-padded in k, bf16 hi/lo split
__global__ void k_wprep(const float* __restrict__ W1, const float* __restrict__ W2) {
    int idx = blockIdx.x * blockDim.x + threadIdx.x;
    if (idx < HH * 512) {
        int j = idx >> 9, k = idx & 511;
        float v = (k < FIN) ? W1[k * HH + j] : 0.f;
        __nv_bfloat16 h = __float2bfloat16_rn(v);
        g_W1t_h[idx] = h;
        g_W1t_l[idx] = __float2bfloat16_rn(v - __bfloat162float(h));
    }
    if (idx < HH * 128) {
        int j = idx >> 7, k = idx & 127;
        float v = (k < HH) ? W2[k * HH + j] : 0.f;
        __nv_bfloat16 h = __float2bfloat16_rn(v);
        g_W2t_h[idx] = h;
        g_W2t_l[idx] = __float2bfloat16_rn(v - __bfloat162float(h));
    }
}

// ---------------- tensor-core GEMM via mma.sync (fallback HMMA path) -------
// C[N,96] = A[N,KREAL] @ W[KREAL,96], W pre-transposed/split n-major in Wh/Wl.
// CTA: 128 rows x 96 cols, 8 warps (m16 band each), 12 n8 tiles per warp.
// K chunks of 32 (2 x k16). bf16 hi/lo 3-pass: AhBh + AhBl + AlBh.
template <int KCHUNKS, int KREAL, int LDA, int WLD>
__global__ void __launch_bounds__(256, 2)
k_gemm_mma(const float* __restrict__ A,
           const __nv_bfloat16* __restrict__ Wh,
           const __nv_bfloat16* __restrict__ Wl,
           float* __restrict__ C) {
    __shared__ uint32_t sAh[128][17], sAl[128][17];
    __shared__ uint32_t sBh[HH][17],  sBl[HH][17];
    int tid = threadIdx.x, wid = tid >> 5, lane = tid & 31;
    int r0 = blockIdx.x * 128;

    float acc[12][4];
    #pragma unroll
    for (int t = 0; t < 12; t++)
        #pragma unroll
        for (int j = 0; j < 4; j++) acc[t][j] = 0.f;

    const int qr = lane >> 2, qc = lane & 3;

    for (int c = 0; c < KCHUNKS; c++) {
        int kbase = c * 32;
        int kvp = (KREAL - kbase) >> 1;           // valid fp32 pairs this chunk
        if (kvp > 16) kvp = 16;

        // A chunk: fp32 -> bf16 hi/lo
        #pragma unroll
        for (int it = 0; it < 8; it++) {
            int idx = tid + it * 256;              // 2048 = 128*16
            int r = idx >> 4, kp = idx & 15;
            int gr = r0 + r;
            float2 v = make_float2(0.f, 0.f);
            if (gr < NN && kp < kvp)
                v = *(const float2*)(A + (size_t)gr * LDA + kbase + 2 * kp);
            float hx = __bfloat162float(__float2bfloat16_rn(v.x));
            float hy = __bfloat162float(__float2bfloat16_rn(v.y));
            sAh[r][kp] = pack_bf16(v.x, v.y);
            sAl[r][kp] = pack_bf16(v.x - hx, v.y - hy);
        }
        // B chunk: pre-split bf16, pair-packed reads (96*16 = 1536 u32)
        #pragma unroll
        for (int it = 0; it < 6; it++) {
            int idx = tid + it * 256;
            int n = idx >> 4, kp = idx & 15;
            sBh[n][kp] = *(const uint32_t*)(Wh + (size_t)n * WLD + kbase + 2 * kp);
            sBl[n][kp] = *(const uint32_t*)(Wl + (size_t)n * WLD + kbase + 2 * kp);
        }
        __syncthreads();

        #pragma unroll
        for (int s = 0; s < 2; s++) {
            int kq = s * 8 + qc;
            int ar = wid * 16 + qr;
            uint32_t ah0 = sAh[ar][kq],     ah1 = sAh[ar + 8][kq];
            uint32_t ah2 = sAh[ar][kq + 4], ah3 = sAh[ar + 8][kq + 4];
            uint32_t al0 = sAl[ar][kq],     al1 = sAl[ar + 8][kq];
            uint32_t al2 = sAl[ar][kq + 4], al3 = sAl[ar + 8][kq + 4];
            #pragma unroll
            for (int t = 0; t < 12; t++) {
                int bc = t * 8 + qr;
                uint32_t bh0 = sBh[bc][kq], bh1 = sBh[bc][kq + 4];
                uint32_t bl0 = sBl[bc][kq], bl1 = sBl[bc][kq + 4];
                mma16816(acc[t], ah0, ah1, ah2, ah3, bh0, bh1);
                mma16816(acc[t], ah0, ah1, ah2, ah3, bl0, bl1);
                mma16816(acc[t], al0, al1, al2, al3, bh0, bh1);
            }
        }
        __syncthreads();
    }

    int gr = r0 + wid * 16 + qr;
    #pragma unroll
    for (int t = 0; t < 12; t++) {
        int col = t * 8 + 2 * qc;
        if (gr < NN)
            *(float2*)(C + (size_t)gr * HH + col) = make_float2(acc[t][0], acc[t][1]);
        if (gr + 8 < NN)
            *(float2*)(C + (size_t)(gr + 8) * HH + col) = make_float2(acc[t][2], acc[t][3]);
    }
}

// ---------------- per-view elementwise stages ------------------------------
__global__ void k_prescale(const int* __restrict__ perm, int use_perm) {
    int idx = blockIdx.x * blockDim.x + threadIdx.x;
    if (idx < NN * HH) {
        int i = idx / HH, j = idx - i * HH;
        int r = use_perm ? perm[i] : i;
        g_B0[idx] = g_norm_out[i] * g_Y[(size_t)r * HH + j];
    }
}

__global__ void k_spmm(const float* __restrict__ in, float* __restrict__ out) {
    int warp = (blockIdx.x * blockDim.x + threadIdx.x) >> 5;
    if (warp >= NN) return;
    int lane = threadIdx.x & 31;
    int b = g_off[warp], e = g_off[warp + 1];
    float a0 = 0.f, a1 = 0.f, a2 = 0.f;
    for (int p = b; p < e; p++) {
        const float* row = in + (size_t)g_csr[p] * HH;
        a0 += __ldg(row + lane);
        a1 += __ldg(row + lane + 32);
        a2 += __ldg(row + lane + 64);
    }
    float* o = out + (size_t)warp * HH;
    o[lane] = a0; o[lane + 32] = a1; o[lane + 64] = a2;
}

__global__ void k_post1(const float* __restrict__ b1, const float* __restrict__ a1) {
    int idx = blockIdx.x * blockDim.x + threadIdx.x;
    if (idx < NN * HH) {
        int i = idx / HH, j = idx - i * HH;
        float h = g_B1[idx] * g_norm_in[i] + b1[j];
        h = (h >= 0.f) ? h : a1[j] * h;
        g_B0[idx] = g_norm_out[i] * h;
    }
}

__global__ void k_final(const float* __restrict__ b2, const float* __restrict__ a2,
                        float* __restrict__ out) {
    int warp = (blockIdx.x * blockDim.x + threadIdx.x) >> 5;
    if (warp >= NN) return;
    int lane = threadIdx.x & 31;
    float nin = g_norm_in[warp];
    float s = 0.f;
    #pragma unroll
    for (int c = 0; c < 3; c++) {
        int j = lane + c * 32;
        float h = g_B1[(size_t)warp * HH + j] * nin + b2[j];
        h = (h >= 0.f) ? h : a2[j] * h;
        s += h * g_wmsum[j];
    }
    #pragma unroll
    for (int o = 16; o; o >>= 1) s += __shfl_down_sync(0xffffffffu, s, o);
    if (lane == 0) out[warp] = s + g_bmsum;
}

// ---------------- launch ----------------------------------------------------
extern "C" void kernel_launch(void* const* d_in, const int* in_sizes, int n_in,
                              void* d_out, int out_size) {
    const float* x    = (const float*)d_in[0];
    const int*   src  = (const int*)  d_in[1];
    const int*   dst  = (const int*)  d_in[2];
    const int*   perm = (const int*)  d_in[3];
    const float* W1   = (const float*)d_in[4];
    const float* b1   = (const float*)d_in[5];
    const float* a1   = (const float*)d_in[6];
    const float* W2   = (const float*)d_in[7];
    const float* b2   = (const float*)d_in[8];
    const float* a2   = (const float*)d_in[9];
    const float* Wm   = (const float*)d_in[10];
    const float* bm   = (const float*)d_in[11];
    float* out = (float*)d_out;

    float *pY = nullptr, *pB0 = nullptr, *pB1 = nullptr, *pB2 = nullptr;
    __nv_bfloat16 *pW1h, *pW1l, *pW2h, *pW2l;
    cudaGetSymbolAddress((void**)&pY,  g_Y);
    cudaGetSymbolAddress((void**)&pB0, g_B0);
    cudaGetSymbolAddress((void**)&pB1, g_B1);
    cudaGetSymbolAddress((void**)&pB2, g_B2);
    cudaGetSymbolAddress((void**)&pW1h, g_W1t_h);
    cudaGetSymbolAddress((void**)&pW1l, g_W1t_l);
    cudaGetSymbolAddress((void**)&pW2h, g_W2t_h);
    cudaGetSymbolAddress((void**)&pW2l, g_W2t_l);

    const int GN  = (NN + 255) / 256;
    const int GE  = (EE + 255) / 256;
    const int GNH = (NN * HH + 255) / 256;
    const int GW  = (NN * 32 + 255) / 256;
    const int GT  = (NN + 127) / 128;   // GEMM blocks (128 rows each)

    k_zero_deg<<<GN, 256>>>();
    k_count<<<GE, 256>>>(src, dst);
    k_scan<<<1, 1024>>>();
    k_norm<<<GN, 256>>>();
    k_scatter<<<GE, 256>>>(src, dst);
    k_wmsum<<<1, 128>>>(Wm, bm);
    k_wprep<<<(HH * 512 + 255) / 256, 256>>>(W1, W2);

    // Y = x @ W1 once, shared by both views (tensor cores, bf16 hi/lo split)
    k_gemm_mma<16, FIN, FIN, 512><<<GT, 256>>>(x, pW1h, pW1l, pY);

    for (int v = 0; v < 2; v++) {
        k_prescale<<<GNH, 256>>>(perm, v);
        k_spmm<<<GW, 256>>>(pB0, pB1);
        k_post1<<<GNH, 256>>>(b1, a1);
        k_gemm_mma<3, HH, HH, 128><<<GT, 256>>>(pB0, pW2h, pW2l, pB2);
        k_spmm<<<GW, 256>>>(pB2, pB1);
        k_final<<<GW, 256>>>(b2, a2, out + (size_t)v * NN);
    }
}

// round 4
// speedup vs baseline: 1.6049x; 1.1763x over previous
#include <cuda_runtime.h>
#include <cuda_bf16.h>
#include <cstdint>

#define NN 50000
#define EE 800000
#define FIN 500
#define HH 96

// ---------------- scratch (device globals; no allocation allowed) ----------
__device__ int   g_deg_out[NN];
__device__ int   g_deg_in[NN];
__device__ int   g_off[NN + 1];
__device__ int   g_cur[NN];
__device__ int   g_csr[EE];    // src per CSR slot (view 0 rows)
__device__ int   g_csr2[EE];   // perm[src] per CSR slot (view 1 rows)
__device__ float g_ew[EE];     // norm_out[src] per CSR slot
__device__ float g_Y [NN * HH];        // x @ W1 (shared by both views)
__device__ float g_B0[2 * NN * HH];    // fused layer-1 output (both views)
__device__ float g_B2[2 * NN * HH];    // B0 @ W2 (both views)
__device__ float g_wmsum[HH];
__device__ float g_bmsum;
// transposed (n-major, k-contiguous), zero-padded, bf16 hi/lo weight copies
__device__ __nv_bfloat16 g_W1t_h[HH * 512];
__device__ __nv_bfloat16 g_W1t_l[HH * 512];
__device__ __nv_bfloat16 g_W2t_h[HH * 128];
__device__ __nv_bfloat16 g_W2t_l[HH * 128];

// ---------------- helpers ----------------------------------------------------
__device__ __forceinline__ uint32_t pack_bf16(float x, float y) {
    __nv_bfloat162 t;
    t.x = __float2bfloat16_rn(x);
    t.y = __float2bfloat16_rn(y);
    return *reinterpret_cast<uint32_t*>(&t);
}

__device__ __forceinline__ void mma16816(float* c, uint32_t a0, uint32_t a1,
                                         uint32_t a2, uint32_t a3,
                                         uint32_t b0, uint32_t b1) {
    asm volatile(
        "mma.sync.aligned.m16n8k16.row.col.f32.bf16.bf16.f32 "
        "{%0,%1,%2,%3}, {%4,%5,%6,%7}, {%8,%9}, {%0,%1,%2,%3};"
        : "+f"(c[0]), "+f"(c[1]), "+f"(c[2]), "+f"(c[3])
        : "r"(a0), "r"(a1), "r"(a2), "r"(a3), "r"(b0), "r"(b1));
}

// ---------------- setup kernels --------------------------------------------
__global__ void k_zero_deg() {
    int i = blockIdx.x * blockDim.x + threadIdx.x;
    if (i < NN) { g_deg_out[i] = 0; g_deg_in[i] = 0; }
}

__global__ void k_count(const int* __restrict__ src, const int* __restrict__ dst) {
    int e = blockIdx.x * blockDim.x + threadIdx.x;
    if (e < EE) {
        atomicAdd(&g_deg_out[src[e]], 1);
        atomicAdd(&g_deg_in[dst[e]], 1);
    }
}

// single-block exclusive scan of g_deg_in -> g_off, copy into g_cur
__global__ void k_scan() {
    const int T  = 1024;
    const int CH = (NN + T - 1) / T;
    int t = threadIdx.x;
    int b = t * CH;
    int e = min(b + CH, NN);

    int s = 0;
    for (int i = b; i < e; i++) s += g_deg_in[i];

    int lane = t & 31, wid = t >> 5;
    int inc = s;
    #pragma unroll
    for (int o = 1; o < 32; o <<= 1) {
        int u = __shfl_up_sync(0xffffffffu, inc, o);
        if (lane >= o) inc += u;
    }
    __shared__ int wsum[32];
    if (lane == 31) wsum[wid] = inc;
    __syncthreads();
    if (wid == 0) {
        int w = wsum[lane];
        #pragma unroll
        for (int o = 1; o < 32; o <<= 1) {
            int u = __shfl_up_sync(0xffffffffu, w, o);
            if (lane >= o) w += u;
        }
        wsum[lane] = w;
    }
    __syncthreads();
    int run = inc - s + (wid ? wsum[wid - 1] : 0);

    for (int i = b; i < e; i++) {
        g_off[i] = run;
        g_cur[i] = run;
        run += g_deg_in[i];
    }
    if (b < NN && e == NN) g_off[NN] = run;
}

// build CSR + per-edge weight + permuted-row index in one pass
__global__ void k_scatter(const int* __restrict__ src, const int* __restrict__ dst,
                          const int* __restrict__ perm) {
    int e = blockIdx.x * blockDim.x + threadIdx.x;
    if (e < EE) {
        int s = src[e];
        int p = atomicAdd(&g_cur[dst[e]], 1);
        g_csr[p]  = s;
        g_csr2[p] = perm[s];
        g_ew[p]   = rsqrtf((float)max(g_deg_out[s], 1));
    }
}

// weight prep: transpose/pad/split W1,W2 to bf16 hi/lo; block 0 also does wmsum
__global__ void k_wprep(const float* __restrict__ W1, const float* __restrict__ W2,
                        const float* __restrict__ Wm, const float* __restrict__ bm) {
    int idx = blockIdx.x * blockDim.x + threadIdx.x;
    if (idx < HH * 512) {
        int j = idx >> 9, k = idx & 511;
        float v = (k < FIN) ? W1[k * HH + j] : 0.f;
        __nv_bfloat16 h = __float2bfloat16_rn(v);
        g_W1t_h[idx] = h;
        g_W1t_l[idx] = __float2bfloat16_rn(v - __bfloat162float(h));
    }
    if (idx < HH * 128) {
        int j = idx >> 7, k = idx & 127;
        float v = (k < HH) ? W2[k * HH + j] : 0.f;
        __nv_bfloat16 h = __float2bfloat16_rn(v);
        g_W2t_h[idx] = h;
        g_W2t_l[idx] = __float2bfloat16_rn(v - __bfloat162float(h));
    }
    if (blockIdx.x == 0 && threadIdx.x < HH) {
        int k = threadIdx.x;
        float s = 0.f;
        for (int j = 0; j < HH; j++) s += Wm[k * HH + j];
        g_wmsum[k] = s;
        if (k == 0) {
            float sb = 0.f;
            for (int j = 0; j < HH; j++) sb += bm[j];
            g_bmsum = sb;
        }
    }
}

// ---------------- tensor-core GEMM via mma.sync (fallback HMMA path) -------
// C[NROWS,96] = A[NROWS,LDA] @ W (pre-transposed/split n-major in Wh/Wl).
// CTA: 128 rows x 96 cols, 8 warps (m16 band each), 12 n8 tiles per warp.
// K chunks of 32 (2 x k16). bf16 hi/lo 3-pass: AhBh + AhBl + AlBh.
template <int KCHUNKS, int KREAL, int LDA, int WLD, int NROWS>
__global__ void __launch_bounds__(256, 2)
k_gemm_mma(const float* __restrict__ A,
           const __nv_bfloat16* __restrict__ Wh,
           const __nv_bfloat16* __restrict__ Wl,
           float* __restrict__ C) {
    __shared__ uint32_t sAh[128][17], sAl[128][17];
    __shared__ uint32_t sBh[HH][17],  sBl[HH][17];
    int tid = threadIdx.x, wid = tid >> 5, lane = tid & 31;
    int r0 = blockIdx.x * 128;

    float acc[12][4];
    #pragma unroll
    for (int t = 0; t < 12; t++)
        #pragma unroll
        for (int j = 0; j < 4; j++) acc[t][j] = 0.f;

    const int qr = lane >> 2, qc = lane & 3;

    for (int c = 0; c < KCHUNKS; c++) {
        int kbase = c * 32;
        int kvp = (KREAL - kbase) >> 1;
        if (kvp > 16) kvp = 16;

        #pragma unroll
        for (int it = 0; it < 8; it++) {
            int idx = tid + it * 256;
            int r = idx >> 4, kp = idx & 15;
            int gr = r0 + r;
            float2 v = make_float2(0.f, 0.f);
            if (gr < NROWS && kp < kvp)
                v = *(const float2*)(A + (size_t)gr * LDA + kbase + 2 * kp);
            float hx = __bfloat162float(__float2bfloat16_rn(v.x));
            float hy = __bfloat162float(__float2bfloat16_rn(v.y));
            sAh[r][kp] = pack_bf16(v.x, v.y);
            sAl[r][kp] = pack_bf16(v.x - hx, v.y - hy);
        }
        #pragma unroll
        for (int it = 0; it < 6; it++) {
            int idx = tid + it * 256;
            int n = idx >> 4, kp = idx & 15;
            sBh[n][kp] = *(const uint32_t*)(Wh + (size_t)n * WLD + kbase + 2 * kp);
            sBl[n][kp] = *(const uint32_t*)(Wl + (size_t)n * WLD + kbase + 2 * kp);
        }
        __syncthreads();

        #pragma unroll
        for (int s = 0; s < 2; s++) {
            int kq = s * 8 + qc;
            int ar = wid * 16 + qr;
            uint32_t ah0 = sAh[ar][kq],     ah1 = sAh[ar + 8][kq];
            uint32_t ah2 = sAh[ar][kq + 4], ah3 = sAh[ar + 8][kq + 4];
            uint32_t al0 = sAl[ar][kq],     al1 = sAl[ar + 8][kq];
            uint32_t al2 = sAl[ar][kq + 4], al3 = sAl[ar + 8][kq + 4];
            #pragma unroll
            for (int t = 0; t < 12; t++) {
                int bc = t * 8 + qr;
                uint32_t bh0 = sBh[bc][kq], bh1 = sBh[bc][kq + 4];
                uint32_t bl0 = sBl[bc][kq], bl1 = sBl[bc][kq + 4];
                mma16816(acc[t], ah0, ah1, ah2, ah3, bh0, bh1);
                mma16816(acc[t], ah0, ah1, ah2, ah3, bl0, bl1);
                mma16816(acc[t], al0, al1, al2, al3, bh0, bh1);
            }
        }
        __syncthreads();
    }

    int gr = r0 + wid * 16 + qr;
    #pragma unroll
    for (int t = 0; t < 12; t++) {
        int col = t * 8 + 2 * qc;
        if (gr < NROWS)
            *(float2*)(C + (size_t)gr * HH + col) = make_float2(acc[t][0], acc[t][1]);
        if (gr + 8 < NROWS)
            *(float2*)(C + (size_t)(gr + 8) * HH + col) = make_float2(acc[t][2], acc[t][3]);
    }
}

// ---------------- fused SpMM layer 1 (both views, warp per node) ------------
// B0[n,:] = norm_out[i] * prelu( norm_in[i] * sum_e ew[e]*Y[row_e,:] + b1, a1 )
// where n in [0,2N), i = n mod N, row_e = csr (view0) or csr2 (view1).
__global__ void k_spmm1(const float* __restrict__ b1, const float* __restrict__ a1) {
    int n = (blockIdx.x * blockDim.x + threadIdx.x) >> 5;
    if (n >= 2 * NN) return;
    int lane = threadIdx.x & 31;
    int i = (n < NN) ? n : n - NN;
    const int* __restrict__ rows = (n < NN) ? g_csr : g_csr2;
    int b = g_off[i], e = g_off[i + 1];
    float a0 = 0.f, a1v = 0.f, a2v = 0.f;
    for (int p = b; p < e; p++) {
        float w = g_ew[p];
        const float* row = g_Y + (size_t)rows[p] * HH;
        a0  = fmaf(w, __ldg(row + lane),      a0);
        a1v = fmaf(w, __ldg(row + lane + 32), a1v);
        a2v = fmaf(w, __ldg(row + lane + 64), a2v);
    }
    float nin  = rsqrtf((float)max(g_deg_in[i], 1));
    float nout = rsqrtf((float)max(g_deg_out[i], 1));
    float* o = g_B0 + (size_t)n * HH;
    #pragma unroll
    for (int c = 0; c < 3; c++) {
        int j = lane + c * 32;
        float acc = (c == 0) ? a0 : (c == 1) ? a1v : a2v;
        float h = fmaf(acc, nin, __ldg(b1 + j));
        h = (h >= 0.f) ? h : __ldg(a1 + j) * h;
        o[j] = nout * h;
    }
}

// ---------------- fused SpMM layer 2 + readout (both views) -----------------
// out[n] = bmsum + sum_j wmsum[j]*prelu( norm_in[i]*sum_e B2[vbase+csr_e, j] + b2[j], a2[j] )
__global__ void k_spmm2(const float* __restrict__ b2, const float* __restrict__ a2,
                        float* __restrict__ out) {
    int n = (blockIdx.x * blockDim.x + threadIdx.x) >> 5;
    if (n >= 2 * NN) return;
    int lane = threadIdx.x & 31;
    int i = (n < NN) ? n : n - NN;
    size_t vbase = (n < NN) ? 0 : (size_t)NN;
    int b = g_off[i], e = g_off[i + 1];
    float a0 = 0.f, a1v = 0.f, a2v = 0.f;
    for (int p = b; p < e; p++) {
        const float* row = g_B2 + (vbase + (size_t)g_csr[p]) * HH;
        a0  += __ldg(row + lane);
        a1v += __ldg(row + lane + 32);
        a2v += __ldg(row + lane + 64);
    }
    float nin = rsqrtf((float)max(g_deg_in[i], 1));
    float s = 0.f;
    #pragma unroll
    for (int c = 0; c < 3; c++) {
        int j = lane + c * 32;
        float acc = (c == 0) ? a0 : (c == 1) ? a1v : a2v;
        float h = fmaf(acc, nin, __ldg(b2 + j));
        h = (h >= 0.f) ? h : __ldg(a2 + j) * h;
        s = fmaf(h, g_wmsum[j], s);
    }
    #pragma unroll
    for (int o = 16; o; o >>= 1) s += __shfl_down_sync(0xffffffffu, s, o);
    if (lane == 0) out[n] = s + g_bmsum;
}

// ---------------- launch ----------------------------------------------------
extern "C" void kernel_launch(void* const* d_in, const int* in_sizes, int n_in,
                              void* d_out, int out_size) {
    const float* x    = (const float*)d_in[0];
    const int*   src  = (const int*)  d_in[1];
    const int*   dst  = (const int*)  d_in[2];
    const int*   perm = (const int*)  d_in[3];
    const float* W1   = (const float*)d_in[4];
    const float* b1   = (const float*)d_in[5];
    const float* a1   = (const float*)d_in[6];
    const float* W2   = (const float*)d_in[7];
    const float* b2   = (const float*)d_in[8];
    const float* a2   = (const float*)d_in[9];
    const float* Wm   = (const float*)d_in[10];
    const float* bm   = (const float*)d_in[11];
    float* out = (float*)d_out;

    float *pY, *pB0, *pB2;
    __nv_bfloat16 *pW1h, *pW1l, *pW2h, *pW2l;
    cudaGetSymbolAddress((void**)&pY,  g_Y);
    cudaGetSymbolAddress((void**)&pB0, g_B0);
    cudaGetSymbolAddress((void**)&pB2, g_B2);
    cudaGetSymbolAddress((void**)&pW1h, g_W1t_h);
    cudaGetSymbolAddress((void**)&pW1l, g_W1t_l);
    cudaGetSymbolAddress((void**)&pW2h, g_W2t_h);
    cudaGetSymbolAddress((void**)&pW2l, g_W2t_l);

    const int GN  = (NN + 255) / 256;
    const int GE  = (EE + 255) / 256;
    const int GW2 = (2 * NN * 32 + 255) / 256;       // warp-per-node, both views
    const int GT1 = (NN + 127) / 128;                // GEMM1 blocks
    const int GT2 = (2 * NN + 127) / 128;            // GEMM2 blocks (both views)

    k_zero_deg<<<GN, 256>>>();
    k_count<<<GE, 256>>>(src, dst);
    k_scan<<<1, 1024>>>();
    k_scatter<<<GE, 256>>>(src, dst, perm);
    k_wprep<<<(HH * 512 + 255) / 256, 256>>>(W1, W2, Wm, bm);

    // launch #5 = GEMM1 (ncu profiles this one)
    k_gemm_mma<16, FIN, FIN, 512, NN><<<GT1, 256>>>(x, pW1h, pW1l, pY);

    k_spmm1<<<GW2, 256>>>(b1, a1);
    k_gemm_mma<3, HH, HH, 128, 2 * NN><<<GT2, 256>>>(pB0, pW2h, pW2l, pB2);
    k_spmm2<<<GW2, 256>>>(b2, a2, out);
}

// round 5
// speedup vs baseline: 1.6459x; 1.0255x over previous
#include <cuda_runtime.h>
#include <cuda_bf16.h>
#include <cuda_fp16.h>
#include <cstdint>

#define NN 50000
#define EE 800000
#define FIN 500
#define HH 96

// ---------------- scratch (device globals; no allocation allowed) ----------
__device__ int   g_deg_out[NN];
__device__ int   g_deg_in[NN];
__device__ int   g_off[NN + 1];
__device__ int   g_cur[NN];
__device__ int2  g_csrp[EE];   // {src, perm[src]} per CSR slot
__device__ float g_ew[EE];     // norm_out[src] per CSR slot
__device__ __half g_Yh [NN * HH];       // x @ W1 (fp16, shared by both views)
__device__ float  g_B0[2 * NN * HH];    // fused layer-1 output (both views, fp32)
__device__ __half g_B2h[2 * NN * HH];   // B0 @ W2 (fp16, both views)
__device__ float g_wmsum[HH];
__device__ float g_bmsum;
// transposed (n-major, k-contiguous), zero-padded, bf16 hi/lo weight copies
__device__ __nv_bfloat16 g_W1t_h[HH * 512];
__device__ __nv_bfloat16 g_W1t_l[HH * 512];
__device__ __nv_bfloat16 g_W2t_h[HH * 128];
__device__ __nv_bfloat16 g_W2t_l[HH * 128];

// ---------------- helpers ----------------------------------------------------
__device__ __forceinline__ uint32_t pack_bf16(float x, float y) {
    __nv_bfloat162 t;
    t.x = __float2bfloat16_rn(x);
    t.y = __float2bfloat16_rn(y);
    return *reinterpret_cast<uint32_t*>(&t);
}

__device__ __forceinline__ void mma16816(float* c, uint32_t a0, uint32_t a1,
                                         uint32_t a2, uint32_t a3,
                                         uint32_t b0, uint32_t b1) {
    asm volatile(
        "mma.sync.aligned.m16n8k16.row.col.f32.bf16.bf16.f32 "
        "{%0,%1,%2,%3}, {%4,%5,%6,%7}, {%8,%9}, {%0,%1,%2,%3};"
        : "+f"(c[0]), "+f"(c[1]), "+f"(c[2]), "+f"(c[3])
        : "r"(a0), "r"(a1), "r"(a2), "r"(a3), "r"(b0), "r"(b1));
}

// ---------------- setup kernels --------------------------------------------
__global__ void k_zero_deg() {
    int i = blockIdx.x * blockDim.x + threadIdx.x;
    if (i < NN) { g_deg_out[i] = 0; g_deg_in[i] = 0; }
}

__global__ void k_count(const int* __restrict__ src, const int* __restrict__ dst) {
    int e = blockIdx.x * blockDim.x + threadIdx.x;
    if (e < EE) {
        atomicAdd(&g_deg_out[src[e]], 1);
        atomicAdd(&g_deg_in[dst[e]], 1);
    }
}

// single-block exclusive scan of g_deg_in -> g_off, copy into g_cur
__global__ void k_scan() {
    const int T  = 1024;
    const int CH = (NN + T - 1) / T;
    int t = threadIdx.x;
    int b = t * CH;
    int e = min(b + CH, NN);

    int s = 0;
    for (int i = b; i < e; i++) s += g_deg_in[i];

    int lane = t & 31, wid = t >> 5;
    int inc = s;
    #pragma unroll
    for (int o = 1; o < 32; o <<= 1) {
        int u = __shfl_up_sync(0xffffffffu, inc, o);
        if (lane >= o) inc += u;
    }
    __shared__ int wsum[32];
    if (lane == 31) wsum[wid] = inc;
    __syncthreads();
    if (wid == 0) {
        int w = wsum[lane];
        #pragma unroll
        for (int o = 1; o < 32; o <<= 1) {
            int u = __shfl_up_sync(0xffffffffu, w, o);
            if (lane >= o) w += u;
        }
        wsum[lane] = w;
    }
    __syncthreads();
    int run = inc - s + (wid ? wsum[wid - 1] : 0);

    for (int i = b; i < e; i++) {
        g_off[i] = run;
        g_cur[i] = run;
        run += g_deg_in[i];
    }
    if (b < NN && e == NN) g_off[NN] = run;
}

// build CSR (+permuted row) + per-edge weight in one pass
__global__ void k_scatter(const int* __restrict__ src, const int* __restrict__ dst,
                          const int* __restrict__ perm) {
    int e = blockIdx.x * blockDim.x + threadIdx.x;
    if (e < EE) {
        int s = src[e];
        int p = atomicAdd(&g_cur[dst[e]], 1);
        g_csrp[p] = make_int2(s, perm[s]);
        g_ew[p]   = rsqrtf((float)max(g_deg_out[s], 1));
    }
}

// weight prep: transpose/pad/split W1,W2 to bf16 hi/lo; block 0 also does wmsum
__global__ void k_wprep(const float* __restrict__ W1, const float* __restrict__ W2,
                        const float* __restrict__ Wm, const float* __restrict__ bm) {
    int idx = blockIdx.x * blockDim.x + threadIdx.x;
    if (idx < HH * 512) {
        int j = idx >> 9, k = idx & 511;
        float v = (k < FIN) ? W1[k * HH + j] : 0.f;
        __nv_bfloat16 h = __float2bfloat16_rn(v);
        g_W1t_h[idx] = h;
        g_W1t_l[idx] = __float2bfloat16_rn(v - __bfloat162float(h));
    }
    if (idx < HH * 128) {
        int j = idx >> 7, k = idx & 127;
        float v = (k < HH) ? W2[k * HH + j] : 0.f;
        __nv_bfloat16 h = __float2bfloat16_rn(v);
        g_W2t_h[idx] = h;
        g_W2t_l[idx] = __float2bfloat16_rn(v - __bfloat162float(h));
    }
    if (blockIdx.x == 0 && threadIdx.x < HH) {
        int k = threadIdx.x;
        float s = 0.f;
        for (int j = 0; j < HH; j++) s += Wm[k * HH + j];
        g_wmsum[k] = s;
        if (k == 0) {
            float sb = 0.f;
            for (int j = 0; j < HH; j++) sb += bm[j];
            g_bmsum = sb;
        }
    }
}

// ---------------- tensor-core GEMM via mma.sync (fallback HMMA path) -------
// C[NROWS,96](fp16) = A[NROWS,LDA](fp32) @ W (pre-split n-major bf16 Wh/Wl).
// CTA: 128 rows x 96 cols, 8 warps as 4(m) x 2(n): each warp 32 rows x 48 cols
// (2 m16 bands x 6 n8 tiles). K chunks of 32 (2 x k16).
// bf16 hi/lo 3-pass: AhBh + AhBl + AlBh.
template <int KCHUNKS, int KREAL, int LDA, int WLD, int NROWS>
__global__ void __launch_bounds__(256, 2)
k_gemm_mma(const float* __restrict__ A,
           const __nv_bfloat16* __restrict__ Wh,
           const __nv_bfloat16* __restrict__ Wl,
           __half* __restrict__ C) {
    __shared__ uint32_t sAh[128][17], sAl[128][17];
    __shared__ uint32_t sBh[HH][17],  sBl[HH][17];
    int tid = threadIdx.x, wid = tid >> 5, lane = tid & 31;
    int mw = wid >> 1, nw = wid & 1;
    int r0 = blockIdx.x * 128;

    float acc[2][6][4];
    #pragma unroll
    for (int b = 0; b < 2; b++)
        #pragma unroll
        for (int t = 0; t < 6; t++)
            #pragma unroll
            for (int j = 0; j < 4; j++) acc[b][t][j] = 0.f;

    const int qr = lane >> 2, qc = lane & 3;

    for (int c = 0; c < KCHUNKS; c++) {
        int kbase = c * 32;
        int kvp = (KREAL - kbase) >> 1;
        if (kvp > 16) kvp = 16;

        #pragma unroll
        for (int it = 0; it < 8; it++) {
            int idx = tid + it * 256;
            int r = idx >> 4, kp = idx & 15;
            int gr = r0 + r;
            float2 v = make_float2(0.f, 0.f);
            if (gr < NROWS && kp < kvp)
                v = *(const float2*)(A + (size_t)gr * LDA + kbase + 2 * kp);
            float hx = __bfloat162float(__float2bfloat16_rn(v.x));
            float hy = __bfloat162float(__float2bfloat16_rn(v.y));
            sAh[r][kp] = pack_bf16(v.x, v.y);
            sAl[r][kp] = pack_bf16(v.x - hx, v.y - hy);
        }
        #pragma unroll
        for (int it = 0; it < 6; it++) {
            int idx = tid + it * 256;
            int n = idx >> 4, kp = idx & 15;
            sBh[n][kp] = *(const uint32_t*)(Wh + (size_t)n * WLD + kbase + 2 * kp);
            sBl[n][kp] = *(const uint32_t*)(Wl + (size_t)n * WLD + kbase + 2 * kp);
        }
        __syncthreads();

        #pragma unroll
        for (int s = 0; s < 2; s++) {
            int kq = s * 8 + qc;
            uint32_t bh[6][2], bl[6][2];
            #pragma unroll
            for (int t = 0; t < 6; t++) {
                int bc = nw * 48 + t * 8 + qr;
                bh[t][0] = sBh[bc][kq]; bh[t][1] = sBh[bc][kq + 4];
                bl[t][0] = sBl[bc][kq]; bl[t][1] = sBl[bc][kq + 4];
            }
            #pragma unroll
            for (int b = 0; b < 2; b++) {
                int ar = mw * 32 + b * 16 + qr;
                uint32_t ah0 = sAh[ar][kq],     ah1 = sAh[ar + 8][kq];
                uint32_t ah2 = sAh[ar][kq + 4], ah3 = sAh[ar + 8][kq + 4];
                uint32_t al0 = sAl[ar][kq],     al1 = sAl[ar + 8][kq];
                uint32_t al2 = sAl[ar][kq + 4], al3 = sAl[ar + 8][kq + 4];
                #pragma unroll
                for (int t = 0; t < 6; t++) {
                    mma16816(acc[b][t], ah0, ah1, ah2, ah3, bh[t][0], bh[t][1]);
                    mma16816(acc[b][t], ah0, ah1, ah2, ah3, bl[t][0], bl[t][1]);
                    mma16816(acc[b][t], al0, al1, al2, al3, bh[t][0], bh[t][1]);
                }
            }
        }
        __syncthreads();
    }

    #pragma unroll
    for (int b = 0; b < 2; b++) {
        int gr = r0 + mw * 32 + b * 16 + qr;
        #pragma unroll
        for (int t = 0; t < 6; t++) {
            int col = nw * 48 + t * 8 + 2 * qc;
            if (gr < NROWS)
                *(__half2*)(C + (size_t)gr * HH + col) =
                    __floats2half2_rn(acc[b][t][0], acc[b][t][1]);
            if (gr + 8 < NROWS)
                *(__half2*)(C + (size_t)(gr + 8) * HH + col) =
                    __floats2half2_rn(acc[b][t][2], acc[b][t][3]);
        }
    }
}

// ---------------- fused SpMM layer 1 (both views, warp per node) ------------
// B0[n,:] = norm_out[i] * prelu( norm_in[i] * sum_e ew[e]*Yh[row_e,:] + b1, a1 )
__global__ void k_spmm1(const float* __restrict__ b1, const float* __restrict__ a1) {
    int n = (blockIdx.x * blockDim.x + threadIdx.x) >> 5;
    if (n >= 2 * NN) return;
    int lane = threadIdx.x & 31;
    int view1 = (n >= NN);
    int i = view1 ? n - NN : n;
    int b = g_off[i], e = g_off[i + 1];
    float a0 = 0.f, a1v = 0.f, a2v = 0.f;
    for (int p = b; p < e; p++) {
        float w = g_ew[p];
        int2 rp = g_csrp[p];
        int row = view1 ? rp.y : rp.x;
        const __half* hrow = g_Yh + (size_t)row * HH;
        a0  = fmaf(w, __half2float(__ldg(hrow + lane)),      a0);
        a1v = fmaf(w, __half2float(__ldg(hrow + lane + 32)), a1v);
        a2v = fmaf(w, __half2float(__ldg(hrow + lane + 64)), a2v);
    }
    float nin  = rsqrtf((float)max(g_deg_in[i], 1));
    float nout = rsqrtf((float)max(g_deg_out[i], 1));
    float* o = g_B0 + (size_t)n * HH;
    #pragma unroll
    for (int c = 0; c < 3; c++) {
        int j = lane + c * 32;
        float acc = (c == 0) ? a0 : (c == 1) ? a1v : a2v;
        float h = fmaf(acc, nin, __ldg(b1 + j));
        h = (h >= 0.f) ? h : __ldg(a1 + j) * h;
        o[j] = nout * h;
    }
}

// ---------------- fused SpMM layer 2 + readout (both views) -----------------
__global__ void k_spmm2(const float* __restrict__ b2, const float* __restrict__ a2,
                        float* __restrict__ out) {
    int n = (blockIdx.x * blockDim.x + threadIdx.x) >> 5;
    if (n >= 2 * NN) return;
    int lane = threadIdx.x & 31;
    int i = (n < NN) ? n : n - NN;
    size_t vbase = (n < NN) ? 0 : (size_t)NN;
    int b = g_off[i], e = g_off[i + 1];
    float a0 = 0.f, a1v = 0.f, a2v = 0.f;
    for (int p = b; p < e; p++) {
        const __half* row = g_B2h + (vbase + (size_t)g_csrp[p].x) * HH;
        a0  += __half2float(__ldg(row + lane));
        a1v += __half2float(__ldg(row + lane + 32));
        a2v += __half2float(__ldg(row + lane + 64));
    }
    float nin = rsqrtf((float)max(g_deg_in[i], 1));
    float s = 0.f;
    #pragma unroll
    for (int c = 0; c < 3; c++) {
        int j = lane + c * 32;
        float acc = (c == 0) ? a0 : (c == 1) ? a1v : a2v;
        float h = fmaf(acc, nin, __ldg(b2 + j));
        h = (h >= 0.f) ? h : __ldg(a2 + j) * h;
        s = fmaf(h, g_wmsum[j], s);
    }
    #pragma unroll
    for (int o = 16; o; o >>= 1) s += __shfl_down_sync(0xffffffffu, s, o);
    if (lane == 0) out[n] = s + g_bmsum;
}

// ---------------- launch ----------------------------------------------------
extern "C" void kernel_launch(void* const* d_in, const int* in_sizes, int n_in,
                              void* d_out, int out_size) {
    const float* x    = (const float*)d_in[0];
    const int*   src  = (const int*)  d_in[1];
    const int*   dst  = (const int*)  d_in[2];
    const int*   perm = (const int*)  d_in[3];
    const float* W1   = (const float*)d_in[4];
    const float* b1   = (const float*)d_in[5];
    const float* a1   = (const float*)d_in[6];
    const float* W2   = (const float*)d_in[7];
    const float* b2   = (const float*)d_in[8];
    const float* a2   = (const float*)d_in[9];
    const float* Wm   = (const float*)d_in[10];
    const float* bm   = (const float*)d_in[11];
    float* out = (float*)d_out;

    float *pB0;
    __half *pYh, *pB2h;
    __nv_bfloat16 *pW1h, *pW1l, *pW2h, *pW2l;
    cudaGetSymbolAddress((void**)&pYh,  g_Yh);
    cudaGetSymbolAddress((void**)&pB0,  g_B0);
    cudaGetSymbolAddress((void**)&pB2h, g_B2h);
    cudaGetSymbolAddress((void**)&pW1h, g_W1t_h);
    cudaGetSymbolAddress((void**)&pW1l, g_W1t_l);
    cudaGetSymbolAddress((void**)&pW2h, g_W2t_h);
    cudaGetSymbolAddress((void**)&pW2l, g_W2t_l);

    const int GN  = (NN + 255) / 256;
    const int GE  = (EE + 255) / 256;
    const int GW2 = (2 * NN * 32 + 255) / 256;       // warp-per-node, both views
    const int GT1 = (NN + 127) / 128;                // GEMM1 blocks
    const int GT2 = (2 * NN + 127) / 128;            // GEMM2 blocks (both views)

    k_zero_deg<<<GN, 256>>>();
    k_count<<<GE, 256>>>(src, dst);
    k_scan<<<1, 1024>>>();
    k_scatter<<<GE, 256>>>(src, dst, perm);
    k_wprep<<<(HH * 512 + 255) / 256, 256>>>(W1, W2, Wm, bm);

    // launch #5 = GEMM1 (ncu profiles this one)
    k_gemm_mma<16, FIN, FIN, 512, NN><<<GT1, 256>>>(x, pW1h, pW1l, pYh);

    k_spmm1<<<GW2, 256>>>(b1, a1);
    k_gemm_mma<3, HH, HH, 128, 2 * NN><<<GT2, 256>>>(pB0, pW2h, pW2l, pB2h);
    k_spmm2<<<GW2, 256>>>(b2, a2, out);
}

// round 6
// speedup vs baseline: 1.7705x; 1.0757x over previous
#include <cuda_runtime.h>
#include <cuda_bf16.h>
#include <cuda_fp16.h>
#include <cstdint>

#define NN 50000
#define EE 800000
#define FIN 500
#define HH 96

// ---------------- scratch (device globals; no allocation allowed) ----------
__device__ int    g_deg_out[NN];
__device__ int    g_deg_in[NN];
__device__ int    g_off[NN + 1];
__device__ int    g_cur[NN];
__device__ int    g_csr[EE];             // src per CSR slot
__device__ __half g_Yplain[NN * HH];     // x @ W1, fp16 (for perm gather)
__device__ __half g_Y01[NN * 2 * HH];    // [norm_out*Y | norm_out*Y[perm]] per node
__device__ __half g_B0h[2 * NN * HH];    // layer-1 out, row n=2i+v, fp16
__device__ __half g_B2h[2 * NN * HH];    // B0 @ W2, row n=2i+v, fp16
__device__ float  g_wmsum[HH];
__device__ float  g_bmsum;
// transposed (n-major, k-contiguous), zero-padded, bf16 hi/lo weight copies
__device__ __nv_bfloat16 g_W1t_h[HH * 512];
__device__ __nv_bfloat16 g_W1t_l[HH * 512];
__device__ __nv_bfloat16 g_W2t_h[HH * 128];
__device__ __nv_bfloat16 g_W2t_l[HH * 128];

// ---------------- helpers ----------------------------------------------------
__device__ __forceinline__ uint32_t pack_bf16(float x, float y) {
    __nv_bfloat162 t;
    t.x = __float2bfloat16_rn(x);
    t.y = __float2bfloat16_rn(y);
    return *reinterpret_cast<uint32_t*>(&t);
}

__device__ __forceinline__ void mma16816(float* c, uint32_t a0, uint32_t a1,
                                         uint32_t a2, uint32_t a3,
                                         uint32_t b0, uint32_t b1) {
    asm volatile(
        "mma.sync.aligned.m16n8k16.row.col.f32.bf16.bf16.f32 "
        "{%0,%1,%2,%3}, {%4,%5,%6,%7}, {%8,%9}, {%0,%1,%2,%3};"
        : "+f"(c[0]), "+f"(c[1]), "+f"(c[2]), "+f"(c[3])
        : "r"(a0), "r"(a1), "r"(a2), "r"(a3), "r"(b0), "r"(b1));
}

// ---------------- setup kernels --------------------------------------------
__global__ void k_zero_deg() {
    int i = blockIdx.x * blockDim.x + threadIdx.x;
    if (i < NN) { g_deg_out[i] = 0; g_deg_in[i] = 0; }
}

__global__ void k_count(const int* __restrict__ src, const int* __restrict__ dst) {
    int e = blockIdx.x * blockDim.x + threadIdx.x;
    if (e < EE) {
        atomicAdd(&g_deg_out[src[e]], 1);
        atomicAdd(&g_deg_in[dst[e]], 1);
    }
}

// single-block exclusive scan of g_deg_in -> g_off, copy into g_cur
__global__ void k_scan() {
    const int T  = 1024;
    const int CH = (NN + T - 1) / T;
    int t = threadIdx.x;
    int b = t * CH;
    int e = min(b + CH, NN);

    int s = 0;
    for (int i = b; i < e; i++) s += g_deg_in[i];

    int lane = t & 31, wid = t >> 5;
    int inc = s;
    #pragma unroll
    for (int o = 1; o < 32; o <<= 1) {
        int u = __shfl_up_sync(0xffffffffu, inc, o);
        if (lane >= o) inc += u;
    }
    __shared__ int wsum[32];
    if (lane == 31) wsum[wid] = inc;
    __syncthreads();
    if (wid == 0) {
        int w = wsum[lane];
        #pragma unroll
        for (int o = 1; o < 32; o <<= 1) {
            int u = __shfl_up_sync(0xffffffffu, w, o);
            if (lane >= o) w += u;
        }
        wsum[lane] = w;
    }
    __syncthreads();
    int run = inc - s + (wid ? wsum[wid - 1] : 0);

    for (int i = b; i < e; i++) {
        g_off[i] = run;
        g_cur[i] = run;
        run += g_deg_in[i];
    }
    if (b < NN && e == NN) g_off[NN] = run;
}

__global__ void k_scatter(const int* __restrict__ src, const int* __restrict__ dst) {
    int e = blockIdx.x * blockDim.x + threadIdx.x;
    if (e < EE) {
        int p = atomicAdd(&g_cur[dst[e]], 1);
        g_csr[p] = src[e];
    }
}

// weight prep: transpose/pad/split W1,W2 to bf16 hi/lo; block 0 also does wmsum
__global__ void k_wprep(const float* __restrict__ W1, const float* __restrict__ W2,
                        const float* __restrict__ Wm, const float* __restrict__ bm) {
    int idx = blockIdx.x * blockDim.x + threadIdx.x;
    if (idx < HH * 512) {
        int j = idx >> 9, k = idx & 511;
        float v = (k < FIN) ? W1[k * HH + j] : 0.f;
        __nv_bfloat16 h = __float2bfloat16_rn(v);
        g_W1t_h[idx] = h;
        g_W1t_l[idx] = __float2bfloat16_rn(v - __bfloat162float(h));
    }
    if (idx < HH * 128) {
        int j = idx >> 7, k = idx & 127;
        float v = (k < HH) ? W2[k * HH + j] : 0.f;
        __nv_bfloat16 h = __float2bfloat16_rn(v);
        g_W2t_h[idx] = h;
        g_W2t_l[idx] = __float2bfloat16_rn(v - __bfloat162float(h));
    }
    if (blockIdx.x == 0 && threadIdx.x < HH) {
        int k = threadIdx.x;
        float s = 0.f;
        for (int j = 0; j < HH; j++) s += Wm[k * HH + j];
        g_wmsum[k] = s;
        if (k == 0) {
            float sb = 0.f;
            for (int j = 0; j < HH; j++) sb += bm[j];
            g_bmsum = sb;
        }
    }
}

// ---------------- tensor-core GEMM via mma.sync (fallback HMMA path) -------
// CTA: 128 rows x 96 cols, 8 warps as 4(m) x 2(n); warp = 2 m16 bands x 6 n8.
// K chunks of 32 (2 x k16). bf16 hi/lo 3-pass: AhBh + AhBl + AlBh.
// HALF_IN: A fp16 (exact hi/lo split). EPI1: write Yplain + scaled Y01 view0.
template <int KCHUNKS, int KREAL, int LDA, int WLD, int NROWS, bool HALF_IN, bool EPI1>
__global__ void __launch_bounds__(256, 2)
k_gemm_mma(const void* __restrict__ Ain,
           const __nv_bfloat16* __restrict__ Wh,
           const __nv_bfloat16* __restrict__ Wl,
           __half* __restrict__ C) {
    __shared__ uint32_t sAh[128][17], sAl[128][17];
    __shared__ uint32_t sBh[HH][17],  sBl[HH][17];
    int tid = threadIdx.x, wid = tid >> 5, lane = tid & 31;
    int mw = wid >> 1, nw = wid & 1;
    int r0 = blockIdx.x * 128;

    float acc[2][6][4];
    #pragma unroll
    for (int b = 0; b < 2; b++)
        #pragma unroll
        for (int t = 0; t < 6; t++)
            #pragma unroll
            for (int j = 0; j < 4; j++) acc[b][t][j] = 0.f;

    const int qr = lane >> 2, qc = lane & 3;

    for (int c = 0; c < KCHUNKS; c++) {
        int kbase = c * 32;
        int kvp = (KREAL - kbase) >> 1;
        if (kvp > 16) kvp = 16;

        #pragma unroll
        for (int it = 0; it < 8; it++) {
            int idx = tid + it * 256;
            int r = idx >> 4, kp = idx & 15;
            int gr = r0 + r;
            float2 v = make_float2(0.f, 0.f);
            if (gr < NROWS && kp < kvp) {
                if (HALF_IN) {
                    __half2 h2 = *(const __half2*)((const __half*)Ain +
                                   (size_t)gr * LDA + kbase + 2 * kp);
                    v = __half22float2(h2);
                } else {
                    v = *(const float2*)((const float*)Ain +
                                   (size_t)gr * LDA + kbase + 2 * kp);
                }
            }
            float hx = __bfloat162float(__float2bfloat16_rn(v.x));
            float hy = __bfloat162float(__float2bfloat16_rn(v.y));
            sAh[r][kp] = pack_bf16(v.x, v.y);
            sAl[r][kp] = pack_bf16(v.x - hx, v.y - hy);
        }
        #pragma unroll
        for (int it = 0; it < 6; it++) {
            int idx = tid + it * 256;
            int n = idx >> 4, kp = idx & 15;
            sBh[n][kp] = *(const uint32_t*)(Wh + (size_t)n * WLD + kbase + 2 * kp);
            sBl[n][kp] = *(const uint32_t*)(Wl + (size_t)n * WLD + kbase + 2 * kp);
        }
        __syncthreads();

        #pragma unroll
        for (int s = 0; s < 2; s++) {
            int kq = s * 8 + qc;
            uint32_t bh[6][2], bl[6][2];
            #pragma unroll
            for (int t = 0; t < 6; t++) {
                int bc = nw * 48 + t * 8 + qr;
                bh[t][0] = sBh[bc][kq]; bh[t][1] = sBh[bc][kq + 4];
                bl[t][0] = sBl[bc][kq]; bl[t][1] = sBl[bc][kq + 4];
            }
            #pragma unroll
            for (int b = 0; b < 2; b++) {
                int ar = mw * 32 + b * 16 + qr;
                uint32_t ah0 = sAh[ar][kq],     ah1 = sAh[ar + 8][kq];
                uint32_t ah2 = sAh[ar][kq + 4], ah3 = sAh[ar + 8][kq + 4];
                uint32_t al0 = sAl[ar][kq],     al1 = sAl[ar + 8][kq];
                uint32_t al2 = sAl[ar][kq + 4], al3 = sAl[ar + 8][kq + 4];
                #pragma unroll
                for (int t = 0; t < 6; t++) {
                    mma16816(acc[b][t], ah0, ah1, ah2, ah3, bh[t][0], bh[t][1]);
                    mma16816(acc[b][t], ah0, ah1, ah2, ah3, bl[t][0], bl[t][1]);
                    mma16816(acc[b][t], al0, al1, al2, al3, bh[t][0], bh[t][1]);
                }
            }
        }
        __syncthreads();
    }

    #pragma unroll
    for (int b = 0; b < 2; b++) {
        int gr = r0 + mw * 32 + b * 16 + qr;
        #pragma unroll
        for (int t = 0; t < 6; t++) {
            int col = nw * 48 + t * 8 + 2 * qc;
            #pragma unroll
            for (int h = 0; h < 2; h++) {
                int row = gr + h * 8;
                if (row < NROWS) {
                    float vx = acc[b][t][2 * h], vy = acc[b][t][2 * h + 1];
                    if (EPI1) {
                        *(__half2*)(C + (size_t)row * HH + col) =
                            __floats2half2_rn(vx, vy);
                        float no = rsqrtf((float)max(g_deg_out[row], 1));
                        *(__half2*)(g_Y01 + (size_t)row * (2 * HH) + col) =
                            __floats2half2_rn(no * vx, no * vy);
                    } else {
                        *(__half2*)(C + (size_t)row * HH + col) =
                            __floats2half2_rn(vx, vy);
                    }
                }
            }
        }
    }
}

// ---------------- fill Y01 view1 slot: norm_out[i] * Yplain[perm[i]] -------
__global__ void k_permscale(const int* __restrict__ perm) {
    int n = (blockIdx.x * blockDim.x + threadIdx.x) >> 5;
    if (n >= NN) return;
    int lane = threadIdx.x & 31;
    if (lane >= 12) return;
    int p = perm[n];
    float no = rsqrtf((float)max(g_deg_out[n], 1));
    uint4 v = *(const uint4*)(g_Yplain + (size_t)p * HH + lane * 8);
    __half2* h2 = (__half2*)&v;
    uint4 o;
    __half2* oh = (__half2*)&o;
    #pragma unroll
    for (int t = 0; t < 4; t++) {
        float2 f = __half22float2(h2[t]);
        oh[t] = __floats2half2_rn(no * f.x, no * f.y);
    }
    *(uint4*)(g_Y01 + (size_t)n * (2 * HH) + HH + lane * 8) = o;
}

// ---------------- fused SpMM layer 1, both views in one pass ----------------
// lanes 0-11: view0 chunks, 16-27: view1 chunks; one uint4 gather per lane/edge.
// B0h[2i+v][:] = norm_out[i]*prelu(norm_in[i]*sum_e Y01[src_e][v*96..] + b1, a1)
__global__ void k_spmm1(const float* __restrict__ b1, const float* __restrict__ a1) {
    __shared__ float sb1[HH], sa1[HH];
    for (int j = threadIdx.x; j < HH; j += blockDim.x) {
        sb1[j] = b1[j];
        sa1[j] = a1[j];
    }
    __syncthreads();

    int n = (blockIdx.x * blockDim.x + threadIdx.x) >> 5;
    if (n >= NN) return;
    int lane = threadIdx.x & 31;
    int view = lane >> 4, chunk = lane & 15;
    bool act = chunk < 12;
    int b = g_off[n], e = g_off[n + 1];

    float acc[8];
    #pragma unroll
    for (int t = 0; t < 8; t++) acc[t] = 0.f;

    size_t loff = (size_t)view * HH + chunk * 8;
    for (int p = b; p < e; p++) {
        int s = g_csr[p];
        if (act) {
            uint4 v = *(const uint4*)(g_Y01 + (size_t)s * (2 * HH) + loff);
            __half2* h2 = (__half2*)&v;
            #pragma unroll
            for (int t = 0; t < 4; t++) {
                float2 f = __half22float2(h2[t]);
                acc[2 * t]     += f.x;
                acc[2 * t + 1] += f.y;
            }
        }
    }

    if (act) {
        float nin  = rsqrtf((float)max(g_deg_in[n], 1));
        float nout = rsqrtf((float)max(g_deg_out[n], 1));
        uint4 o;
        __half2* oh = (__half2*)&o;
        #pragma unroll
        for (int t = 0; t < 4; t++) {
            float r[2];
            #pragma unroll
            for (int u = 0; u < 2; u++) {
                int j = chunk * 8 + 2 * t + u;
                float h = fmaf(acc[2 * t + u], nin, sb1[j]);
                h = (h >= 0.f) ? h : sa1[j] * h;
                r[u] = nout * h;
            }
            oh[t] = __floats2half2_rn(r[0], r[1]);
        }
        *(uint4*)(g_B0h + ((size_t)(2 * n + view)) * HH + chunk * 8) = o;
    }
}

// ---------------- fused SpMM layer 2 + readout, both views ------------------
__global__ void k_spmm2(const float* __restrict__ b2, const float* __restrict__ a2,
                        float* __restrict__ out) {
    __shared__ float sb2[HH], sa2[HH], swm[HH];
    for (int j = threadIdx.x; j < HH; j += blockDim.x) {
        sb2[j] = b2[j];
        sa2[j] = a2[j];
        swm[j] = g_wmsum[j];
    }
    __syncthreads();

    int n = (blockIdx.x * blockDim.x + threadIdx.x) >> 5;
    if (n >= NN) return;
    int lane = threadIdx.x & 31;
    int view = lane >> 4, chunk = lane & 15;
    bool act = chunk < 12;
    int b = g_off[n], e = g_off[n + 1];

    float acc[8];
    #pragma unroll
    for (int t = 0; t < 8; t++) acc[t] = 0.f;

    size_t loff = (size_t)view * HH + chunk * 8;   // row 2s+v, chunk slice
    for (int p = b; p < e; p++) {
        int s = g_csr[p];
        if (act) {
            uint4 v = *(const uint4*)(g_B2h + (size_t)s * (2 * HH) + loff);
            __half2* h2 = (__half2*)&v;
            #pragma unroll
            for (int t = 0; t < 4; t++) {
                float2 f = __half22float2(h2[t]);
                acc[2 * t]     += f.x;
                acc[2 * t + 1] += f.y;
            }
        }
    }

    float part = 0.f;
    if (act) {
        float nin = rsqrtf((float)max(g_deg_in[n], 1));
        #pragma unroll
        for (int t = 0; t < 8; t++) {
            int j = chunk * 8 + t;
            float h = fmaf(acc[t], nin, sb2[j]);
            h = (h >= 0.f) ? h : sa2[j] * h;
            part = fmaf(h, swm[j], part);
        }
    }
    #pragma unroll
    for (int o = 8; o; o >>= 1)
        part += __shfl_down_sync(0xffffffffu, part, o, 16);
    if (chunk == 0) out[(size_t)view * NN + n] = part + g_bmsum;
}

// ---------------- launch ----------------------------------------------------
extern "C" void kernel_launch(void* const* d_in, const int* in_sizes, int n_in,
                              void* d_out, int out_size) {
    const float* x    = (const float*)d_in[0];
    const int*   src  = (const int*)  d_in[1];
    const int*   dst  = (const int*)  d_in[2];
    const int*   perm = (const int*)  d_in[3];
    const float* W1   = (const float*)d_in[4];
    const float* b1   = (const float*)d_in[5];
    const float* a1   = (const float*)d_in[6];
    const float* W2   = (const float*)d_in[7];
    const float* b2   = (const float*)d_in[8];
    const float* a2   = (const float*)d_in[9];
    const float* Wm   = (const float*)d_in[10];
    const float* bm   = (const float*)d_in[11];
    float* out = (float*)d_out;

    __half *pYp, *pB0h, *pB2h;
    __nv_bfloat16 *pW1h, *pW1l, *pW2h, *pW2l;
    cudaGetSymbolAddress((void**)&pYp,  g_Yplain);
    cudaGetSymbolAddress((void**)&pB0h, g_B0h);
    cudaGetSymbolAddress((void**)&pB2h, g_B2h);
    cudaGetSymbolAddress((void**)&pW1h, g_W1t_h);
    cudaGetSymbolAddress((void**)&pW1l, g_W1t_l);
    cudaGetSymbolAddress((void**)&pW2h, g_W2t_h);
    cudaGetSymbolAddress((void**)&pW2l, g_W2t_l);

    const int GN  = (NN + 255) / 256;
    const int GE  = (EE + 255) / 256;
    const int GW  = (NN * 32 + 255) / 256;           // warp-per-node
    const int GT1 = (NN + 127) / 128;                // GEMM1 blocks
    const int GT2 = (2 * NN + 127) / 128;            // GEMM2 blocks (both views)

    k_zero_deg<<<GN, 256>>>();
    k_count<<<GE, 256>>>(src, dst);
    k_scan<<<1, 1024>>>();
    k_scatter<<<GE, 256>>>(src, dst);
    k_wprep<<<(HH * 512 + 255) / 256, 256>>>(W1, W2, Wm, bm);

    // GEMM1: Y = x @ W1; epilogue writes Yplain (fp16) + scaled Y01 view0
    k_gemm_mma<16, FIN, FIN, 512, NN, false, true><<<GT1, 256>>>(x, pW1h, pW1l, pYp);
    k_permscale<<<GW, 256>>>(perm);

    k_spmm1<<<GW, 256>>>(b1, a1);
    k_gemm_mma<3, HH, HH, 128, 2 * NN, true, false><<<GT2, 256>>>(pB0h, pW2h, pW2l, pB2h);
    k_spmm2<<<GW, 256>>>(b2, a2, out);
}

// round 7
// speedup vs baseline: 2.1217x; 1.1984x over previous
#include <cuda_runtime.h>
#include <cuda_bf16.h>
#include <cuda_fp16.h>
#include <cstdint>

#define NN 50000
#define EE 800000
#define FIN 500
#define HH 96

// ---------------- scratch (device globals; no allocation allowed) ----------
__device__ int    g_deg_out[NN];
__device__ int    g_deg_in[NN];
__device__ int    g_off[NN + 1];
__device__ int    g_cur[NN];
__device__ int    g_csr[EE];             // src per CSR slot
__device__ __half g_Yplain[NN * HH];     // x @ W1, fp16 (for perm gather)
__device__ __half g_Y01[NN * 2 * HH];    // [norm_out*Y | norm_out*Y[perm]] per node
__device__ __half g_B0h[2 * NN * HH];    // layer-1 out, row n=2i+v, fp16
__device__ __half g_B2h[2 * NN * HH];    // B0 @ W2, row n=2i+v, fp16
__device__ float  g_wmsum[HH];
__device__ float  g_bmsum;
// transposed (n-major, k-contiguous), zero-padded, bf16 hi/lo weight copies
__device__ __nv_bfloat16 g_W1t_h[HH * 512];
__device__ __nv_bfloat16 g_W1t_l[HH * 512];
__device__ __nv_bfloat16 g_W2t_h[HH * 128];
__device__ __nv_bfloat16 g_W2t_l[HH * 128];

// ---------------- helpers ----------------------------------------------------
__device__ __forceinline__ uint32_t pack_bf16(float x, float y) {
    __nv_bfloat162 t;
    t.x = __float2bfloat16_rn(x);
    t.y = __float2bfloat16_rn(y);
    return *reinterpret_cast<uint32_t*>(&t);
}

__device__ __forceinline__ void mma16816(float* c, uint32_t a0, uint32_t a1,
                                         uint32_t a2, uint32_t a3,
                                         uint32_t b0, uint32_t b1) {
    asm volatile(
        "mma.sync.aligned.m16n8k16.row.col.f32.bf16.bf16.f32 "
        "{%0,%1,%2,%3}, {%4,%5,%6,%7}, {%8,%9}, {%0,%1,%2,%3};"
        : "+f"(c[0]), "+f"(c[1]), "+f"(c[2]), "+f"(c[3])
        : "r"(a0), "r"(a1), "r"(a2), "r"(a3), "r"(b0), "r"(b1));
}

// ---------------- setup kernels --------------------------------------------
__global__ void k_count_out(const int* __restrict__ src) {
    int e = blockIdx.x * blockDim.x + threadIdx.x;
    if (e < EE) atomicAdd(&g_deg_out[src[e]], 1);
}

__global__ void k_count_in(const int* __restrict__ dst) {
    int e = blockIdx.x * blockDim.x + threadIdx.x;
    if (e < EE) atomicAdd(&g_deg_in[dst[e]], 1);
}

// single-block exclusive scan of g_deg_in -> g_off, copy into g_cur
__global__ void k_scan() {
    const int T  = 1024;
    const int CH = (NN + T - 1) / T;
    int t = threadIdx.x;
    int b = t * CH;
    int e = min(b + CH, NN);

    int s = 0;
    for (int i = b; i < e; i++) s += g_deg_in[i];

    int lane = t & 31, wid = t >> 5;
    int inc = s;
    #pragma unroll
    for (int o = 1; o < 32; o <<= 1) {
        int u = __shfl_up_sync(0xffffffffu, inc, o);
        if (lane >= o) inc += u;
    }
    __shared__ int wsum[32];
    if (lane == 31) wsum[wid] = inc;
    __syncthreads();
    if (wid == 0) {
        int w = wsum[lane];
        #pragma unroll
        for (int o = 1; o < 32; o <<= 1) {
            int u = __shfl_up_sync(0xffffffffu, w, o);
            if (lane >= o) w += u;
        }
        wsum[lane] = w;
    }
    __syncthreads();
    int run = inc - s + (wid ? wsum[wid - 1] : 0);

    for (int i = b; i < e; i++) {
        g_off[i] = run;
        g_cur[i] = run;
        run += g_deg_in[i];
    }
    if (b < NN && e == NN) g_off[NN] = run;
}

__global__ void k_scatter(const int* __restrict__ src, const int* __restrict__ dst) {
    int e = blockIdx.x * blockDim.x + threadIdx.x;
    if (e < EE) {
        int p = atomicAdd(&g_cur[dst[e]], 1);
        g_csr[p] = src[e];
    }
}

// weight prep: transpose/pad/split W1,W2 to bf16 hi/lo; block 0 also does wmsum
__global__ void k_wprep(const float* __restrict__ W1, const float* __restrict__ W2,
                        const float* __restrict__ Wm, const float* __restrict__ bm) {
    int idx = blockIdx.x * blockDim.x + threadIdx.x;
    if (idx < HH * 512) {
        int j = idx >> 9, k = idx & 511;
        float v = (k < FIN) ? W1[k * HH + j] : 0.f;
        __nv_bfloat16 h = __float2bfloat16_rn(v);
        g_W1t_h[idx] = h;
        g_W1t_l[idx] = __float2bfloat16_rn(v - __bfloat162float(h));
    }
    if (idx < HH * 128) {
        int j = idx >> 7, k = idx & 127;
        float v = (k < HH) ? W2[k * HH + j] : 0.f;
        __nv_bfloat16 h = __float2bfloat16_rn(v);
        g_W2t_h[idx] = h;
        g_W2t_l[idx] = __float2bfloat16_rn(v - __bfloat162float(h));
    }
    if (blockIdx.x == 0 && threadIdx.x < HH) {
        int k = threadIdx.x;
        float s = 0.f;
        for (int j = 0; j < HH; j++) s += Wm[k * HH + j];
        g_wmsum[k] = s;
        if (k == 0) {
            float sb = 0.f;
            for (int j = 0; j < HH; j++) sb += bm[j];
            g_bmsum = sb;
        }
    }
}

// ---------------- tensor-core GEMM via mma.sync, double-buffered ------------
// CTA: 128 rows x 96 cols, 8 warps as 4(m) x 2(n); warp = 2 m16 bands x 6 n8.
// K chunks of 32 (2 x k16). bf16 hi/lo 3-pass: AhBh + AhBl + AlBh.
// Dynamic SMEM, 2-stage pipeline: prefetch regs -> MMA -> store alt buf -> sync.
#define AB_U32 2176              // 128*17
#define BB_U32 1632              // 96*17
#define GEMM_SMEM ((4 * AB_U32 + 4 * BB_U32) * 4)   // 60928 bytes

template <int KCHUNKS, int KREAL, int LDA, int WLD, int NROWS, bool HALF_IN, bool EPI1>
__global__ void __launch_bounds__(256, 2)
k_gemm_mma(const void* __restrict__ Ain,
           const __nv_bfloat16* __restrict__ Wh,
           const __nv_bfloat16* __restrict__ Wl,
           __half* __restrict__ C) {
    extern __shared__ uint32_t dyn[];
    // layout: [Ah0 Al0 Ah1 Al1 | Bh0 Bl0 Bh1 Bl1]
    uint32_t* const AhB[2] = { dyn,               dyn + 2 * AB_U32 };
    uint32_t* const AlB[2] = { dyn + AB_U32,      dyn + 3 * AB_U32 };
    uint32_t* const bbase  = dyn + 4 * AB_U32;
    uint32_t* const BhB[2] = { bbase,             bbase + 2 * BB_U32 };
    uint32_t* const BlB[2] = { bbase + BB_U32,    bbase + 3 * BB_U32 };

    int tid = threadIdx.x, wid = tid >> 5, lane = tid & 31;
    int mw = wid >> 1, nw = wid & 1;
    int r0 = blockIdx.x * 128;

    float acc[2][6][4];
    #pragma unroll
    for (int b = 0; b < 2; b++)
        #pragma unroll
        for (int t = 0; t < 6; t++)
            #pragma unroll
            for (int j = 0; j < 4; j++) acc[b][t][j] = 0.f;

    const int qr = lane >> 2, qc = lane & 3;

    float2   va[8];
    uint32_t vbh[6], vbl[6];

    // ---- prefetch chunk 0 into regs
    #define LOAD_CHUNK(cc)                                                     \
    {                                                                          \
        int kbase = (cc) * 32;                                                 \
        int kvp = (KREAL - kbase) >> 1;                                        \
        if (kvp > 16) kvp = 16;                                                \
        _Pragma("unroll")                                                      \
        for (int it = 0; it < 8; it++) {                                       \
            int idx = tid + it * 256;                                          \
            int r = idx >> 4, kp = idx & 15;                                   \
            int gr = r0 + r;                                                   \
            float2 v = make_float2(0.f, 0.f);                                  \
            if (gr < NROWS && kp < kvp) {                                      \
                if (HALF_IN) {                                                 \
                    __half2 h2 = *(const __half2*)((const __half*)Ain +        \
                                   (size_t)gr * LDA + kbase + 2 * kp);         \
                    v = __half22float2(h2);                                    \
                } else {                                                       \
                    v = *(const float2*)((const float*)Ain +                   \
                                   (size_t)gr * LDA + kbase + 2 * kp);         \
                }                                                              \
            }                                                                  \
            va[it] = v;                                                        \
        }                                                                      \
        _Pragma("unroll")                                                      \
        for (int it = 0; it < 6; it++) {                                       \
            int idx = tid + it * 256;                                          \
            int n = idx >> 4, kp = idx & 15;                                   \
            vbh[it] = *(const uint32_t*)(Wh + (size_t)n * WLD + kbase + 2 * kp);\
            vbl[it] = *(const uint32_t*)(Wl + (size_t)n * WLD + kbase + 2 * kp);\
        }                                                                      \
    }

    #define STORE_CHUNK(buf)                                                   \
    {                                                                          \
        _Pragma("unroll")                                                      \
        for (int it = 0; it < 8; it++) {                                       \
            int idx = tid + it * 256;                                          \
            int r = idx >> 4, kp = idx & 15;                                   \
            float2 v = va[it];                                                 \
            float hx = __bfloat162float(__float2bfloat16_rn(v.x));             \
            float hy = __bfloat162float(__float2bfloat16_rn(v.y));             \
            AhB[buf][r * 17 + kp] = pack_bf16(v.x, v.y);                       \
            AlB[buf][r * 17 + kp] = pack_bf16(v.x - hx, v.y - hy);             \
        }                                                                      \
        _Pragma("unroll")                                                      \
        for (int it = 0; it < 6; it++) {                                       \
            int idx = tid + it * 256;                                          \
            int n = idx >> 4, kp = idx & 15;                                   \
            BhB[buf][n * 17 + kp] = vbh[it];                                   \
            BlB[buf][n * 17 + kp] = vbl[it];                                   \
        }                                                                      \
    }

    LOAD_CHUNK(0);
    STORE_CHUNK(0);
    __syncthreads();

    for (int c = 0; c < KCHUNKS; c++) {
        if (c + 1 < KCHUNKS) LOAD_CHUNK(c + 1);

        const uint32_t* sAh = AhB[c & 1];
        const uint32_t* sAl = AlB[c & 1];
        const uint32_t* sBh = BhB[c & 1];
        const uint32_t* sBl = BlB[c & 1];

        #pragma unroll
        for (int s = 0; s < 2; s++) {
            int kq = s * 8 + qc;
            uint32_t bh[6][2], bl[6][2];
            #pragma unroll
            for (int t = 0; t < 6; t++) {
                int bc = nw * 48 + t * 8 + qr;
                bh[t][0] = sBh[bc * 17 + kq]; bh[t][1] = sBh[bc * 17 + kq + 4];
                bl[t][0] = sBl[bc * 17 + kq]; bl[t][1] = sBl[bc * 17 + kq + 4];
            }
            #pragma unroll
            for (int b = 0; b < 2; b++) {
                int ar = mw * 32 + b * 16 + qr;
                uint32_t ah0 = sAh[ar * 17 + kq],       ah1 = sAh[(ar + 8) * 17 + kq];
                uint32_t ah2 = sAh[ar * 17 + kq + 4],   ah3 = sAh[(ar + 8) * 17 + kq + 4];
                uint32_t al0 = sAl[ar * 17 + kq],       al1 = sAl[(ar + 8) * 17 + kq];
                uint32_t al2 = sAl[ar * 17 + kq + 4],   al3 = sAl[(ar + 8) * 17 + kq + 4];
                #pragma unroll
                for (int t = 0; t < 6; t++) {
                    mma16816(acc[b][t], ah0, ah1, ah2, ah3, bh[t][0], bh[t][1]);
                    mma16816(acc[b][t], ah0, ah1, ah2, ah3, bl[t][0], bl[t][1]);
                    mma16816(acc[b][t], al0, al1, al2, al3, bh[t][0], bh[t][1]);
                }
            }
        }

        if (c + 1 < KCHUNKS) {
            STORE_CHUNK((c + 1) & 1);
            __syncthreads();
        }
    }

    #pragma unroll
    for (int b = 0; b < 2; b++) {
        int gr = r0 + mw * 32 + b * 16 + qr;
        #pragma unroll
        for (int t = 0; t < 6; t++) {
            int col = nw * 48 + t * 8 + 2 * qc;
            #pragma unroll
            for (int h = 0; h < 2; h++) {
                int row = gr + h * 8;
                if (row < NROWS) {
                    float vx = acc[b][t][2 * h], vy = acc[b][t][2 * h + 1];
                    if (EPI1) {
                        *(__half2*)(C + (size_t)row * HH + col) =
                            __floats2half2_rn(vx, vy);
                        float no = rsqrtf((float)max(g_deg_out[row], 1));
                        *(__half2*)(g_Y01 + (size_t)row * (2 * HH) + col) =
                            __floats2half2_rn(no * vx, no * vy);
                    } else {
                        *(__half2*)(C + (size_t)row * HH + col) =
                            __floats2half2_rn(vx, vy);
                    }
                }
            }
        }
    }
    #undef LOAD_CHUNK
    #undef STORE_CHUNK
}

// ---------------- fill Y01 view1 slot: norm_out[i] * Yplain[perm[i]] -------
__global__ void k_permscale(const int* __restrict__ perm) {
    int n = (blockIdx.x * blockDim.x + threadIdx.x) >> 5;
    if (n >= NN) return;
    int lane = threadIdx.x & 31;
    if (lane >= 12) return;
    int p = perm[n];
    float no = rsqrtf((float)max(g_deg_out[n], 1));
    uint4 v = *(const uint4*)(g_Yplain + (size_t)p * HH + lane * 8);
    __half2* h2 = (__half2*)&v;
    uint4 o;
    __half2* oh = (__half2*)&o;
    #pragma unroll
    for (int t = 0; t < 4; t++) {
        float2 f = __half22float2(h2[t]);
        oh[t] = __floats2half2_rn(no * f.x, no * f.y);
    }
    *(uint4*)(g_Y01 + (size_t)n * (2 * HH) + HH + lane * 8) = o;
}

// ---------------- SpMM gather core: 4x unrolled, 16B/lane -------------------
__device__ __forceinline__ void spmm_gather(const __half* __restrict__ base,
                                            size_t loff, int b, int e, bool act,
                                            float* acc) {
    #pragma unroll
    for (int t = 0; t < 8; t++) acc[t] = 0.f;
    auto addv = [&](uint4 v) {
        __half2* h2 = (__half2*)&v;
        #pragma unroll
        for (int t = 0; t < 4; t++) {
            float2 f = __half22float2(h2[t]);
            acc[2 * t]     += f.x;
            acc[2 * t + 1] += f.y;
        }
    };
    int p = b;
    for (; p + 4 <= e; p += 4) {
        int s0 = g_csr[p], s1 = g_csr[p + 1], s2 = g_csr[p + 2], s3 = g_csr[p + 3];
        if (act) {
            uint4 v0 = *(const uint4*)(base + (size_t)s0 * (2 * HH) + loff);
            uint4 v1 = *(const uint4*)(base + (size_t)s1 * (2 * HH) + loff);
            uint4 v2 = *(const uint4*)(base + (size_t)s2 * (2 * HH) + loff);
            uint4 v3 = *(const uint4*)(base + (size_t)s3 * (2 * HH) + loff);
            addv(v0); addv(v1); addv(v2); addv(v3);
        }
    }
    for (; p < e; p++) {
        int s = g_csr[p];
        if (act) addv(*(const uint4*)(base + (size_t)s * (2 * HH) + loff));
    }
}

// ---------------- fused SpMM layer 1, both views in one pass ----------------
__global__ void k_spmm1(const float* __restrict__ b1, const float* __restrict__ a1) {
    __shared__ float sb1[HH], sa1[HH];
    for (int j = threadIdx.x; j < HH; j += blockDim.x) {
        sb1[j] = b1[j];
        sa1[j] = a1[j];
    }
    __syncthreads();

    int n = (blockIdx.x * blockDim.x + threadIdx.x) >> 5;
    if (n >= NN) return;
    int lane = threadIdx.x & 31;
    int view = lane >> 4, chunk = lane & 15;
    bool act = chunk < 12;
    int b = g_off[n], e = g_off[n + 1];

    float acc[8];
    spmm_gather(g_Y01, (size_t)view * HH + chunk * 8, b, e, act, acc);

    if (act) {
        float nin  = rsqrtf((float)max(g_deg_in[n], 1));
        float nout = rsqrtf((float)max(g_deg_out[n], 1));
        uint4 o;
        __half2* oh = (__half2*)&o;
        #pragma unroll
        for (int t = 0; t < 4; t++) {
            float r[2];
            #pragma unroll
            for (int u = 0; u < 2; u++) {
                int j = chunk * 8 + 2 * t + u;
                float h = fmaf(acc[2 * t + u], nin, sb1[j]);
                h = (h >= 0.f) ? h : sa1[j] * h;
                r[u] = nout * h;
            }
            oh[t] = __floats2half2_rn(r[0], r[1]);
        }
        *(uint4*)(g_B0h + ((size_t)(2 * n + view)) * HH + chunk * 8) = o;
    }
}

// ---------------- fused SpMM layer 2 + readout, both views ------------------
__global__ void k_spmm2(const float* __restrict__ b2, const float* __restrict__ a2,
                        float* __restrict__ out) {
    __shared__ float sb2[HH], sa2[HH], swm[HH];
    for (int j = threadIdx.x; j < HH; j += blockDim.x) {
        sb2[j] = b2[j];
        sa2[j] = a2[j];
        swm[j] = g_wmsum[j];
    }
    __syncthreads();

    int n = (blockIdx.x * blockDim.x + threadIdx.x) >> 5;
    if (n >= NN) return;
    int lane = threadIdx.x & 31;
    int view = lane >> 4, chunk = lane & 15;
    bool act = chunk < 12;
    int b = g_off[n], e = g_off[n + 1];

    float acc[8];
    spmm_gather(g_B2h, (size_t)view * HH + chunk * 8, b, e, act, acc);

    float part = 0.f;
    if (act) {
        float nin = rsqrtf((float)max(g_deg_in[n], 1));
        #pragma unroll
        for (int t = 0; t < 8; t++) {
            int j = chunk * 8 + t;
            float h = fmaf(acc[t], nin, sb2[j]);
            h = (h >= 0.f) ? h : sa2[j] * h;
            part = fmaf(h, swm[j], part);
        }
    }
    #pragma unroll
    for (int o = 8; o; o >>= 1)
        part += __shfl_down_sync(0xffffffffu, part, o, 16);
    if (chunk == 0) out[(size_t)view * NN + n] = part + g_bmsum;
}

// ---------------- launch ----------------------------------------------------
extern "C" void kernel_launch(void* const* d_in, const int* in_sizes, int n_in,
                              void* d_out, int out_size) {
    const float* x    = (const float*)d_in[0];
    const int*   src  = (const int*)  d_in[1];
    const int*   dst  = (const int*)  d_in[2];
    const int*   perm = (const int*)  d_in[3];
    const float* W1   = (const float*)d_in[4];
    const float* b1   = (const float*)d_in[5];
    const float* a1   = (const float*)d_in[6];
    const float* W2   = (const float*)d_in[7];
    const float* b2   = (const float*)d_in[8];
    const float* a2   = (const float*)d_in[9];
    const float* Wm   = (const float*)d_in[10];
    const float* bm   = (const float*)d_in[11];
    float* out = (float*)d_out;

    __half *pYp, *pB0h, *pB2h;
    __nv_bfloat16 *pW1h, *pW1l, *pW2h, *pW2l;
    int *pDegOut, *pDegIn;
    cudaGetSymbolAddress((void**)&pYp,  g_Yplain);
    cudaGetSymbolAddress((void**)&pB0h, g_B0h);
    cudaGetSymbolAddress((void**)&pB2h, g_B2h);
    cudaGetSymbolAddress((void**)&pW1h, g_W1t_h);
    cudaGetSymbolAddress((void**)&pW1l, g_W1t_l);
    cudaGetSymbolAddress((void**)&pW2h, g_W2t_h);
    cudaGetSymbolAddress((void**)&pW2l, g_W2t_l);
    cudaGetSymbolAddress((void**)&pDegOut, g_deg_out);
    cudaGetSymbolAddress((void**)&pDegIn,  g_deg_in);

    // one-time host resources (no device memory)
    static cudaStream_t sB = nullptr;
    static cudaEvent_t evF = nullptr, evS = nullptr;
    if (!sB) {
        cudaStreamCreateWithFlags(&sB, cudaStreamNonBlocking);
        cudaEventCreateWithFlags(&evF, cudaEventDisableTiming);
        cudaEventCreateWithFlags(&evS, cudaEventDisableTiming);
        cudaFuncSetAttribute(k_gemm_mma<16, FIN, FIN, 512, NN, false, true>,
                             cudaFuncAttributeMaxDynamicSharedMemorySize, GEMM_SMEM);
        cudaFuncSetAttribute(k_gemm_mma<3, HH, HH, 128, 2 * NN, true, false>,
                             cudaFuncAttributeMaxDynamicSharedMemorySize, GEMM_SMEM);
    }

    const int GE  = (EE + 255) / 256;
    const int GW  = (NN * 32 + 255) / 256;           // warp-per-node
    const int GT1 = (NN + 127) / 128;                // GEMM1 blocks
    const int GT2 = (2 * NN + 127) / 128;            // GEMM2 blocks (both views)

    // ---- fork: CSR build on side stream, GEMM1 path on main stream --------
    cudaEventRecord(evF, 0);
    cudaStreamWaitEvent(sB, evF, 0);

    // side stream: deg_in -> scan -> scatter
    cudaMemsetAsync(pDegIn, 0, NN * sizeof(int), sB);
    k_count_in<<<GE, 256, 0, sB>>>(dst);
    k_scan<<<1, 1024, 0, sB>>>();
    k_scatter<<<GE, 256, 0, sB>>>(src, dst);
    cudaEventRecord(evS, sB);

    // main stream: deg_out -> wprep -> GEMM1 -> permscale
    cudaMemsetAsync(pDegOut, 0, NN * sizeof(int), 0);
    k_count_out<<<GE, 256>>>(src);
    k_wprep<<<(HH * 512 + 255) / 256, 256>>>(W1, W2, Wm, bm);
    k_gemm_mma<16, FIN, FIN, 512, NN, false, true>
        <<<GT1, 256, GEMM_SMEM>>>(x, pW1h, pW1l, pYp);
    k_permscale<<<GW, 256>>>(perm);

    // join, then the dependent tail
    cudaStreamWaitEvent(0, evS, 0);
    k_spmm1<<<GW, 256>>>(b1, a1);
    k_gemm_mma<3, HH, HH, 128, 2 * NN, true, false>
        <<<GT2, 256, GEMM_SMEM>>>(pB0h, pW2h, pW2l, pB2h);
    k_spmm2<<<GW, 256>>>(b2, a2, out);
}

// round 8
// speedup vs baseline: 2.1664x; 1.0211x over previous
#include <cuda_runtime.h>
#include <cuda_bf16.h>
#include <cuda_fp16.h>
#include <cstdint>

#define NN 50000
#define EE 800000
#define FIN 500
#define HH 96

// ---------------- scratch (device globals; no allocation allowed) ----------
__device__ int    g_deg_out[NN];
__device__ int    g_deg_in[NN];
__device__ int    g_off[NN + 1];
__device__ int    g_cur[NN];
__device__ int    g_csr[EE];             // src per CSR slot
__device__ __half g_Yplain[NN * HH];     // x @ W1, fp16
__device__ __half g_Y01[NN * 2 * HH];    // [norm_out*Y | norm_out*Y[perm]] per node
__device__ __half g_B0h[2 * NN * HH];    // layer-1 out, row n=2i+v, fp16
__device__ __half g_B2h[2 * NN * HH];    // B0 @ W2, row n=2i+v, fp16
__device__ float  g_wmsum[HH];
__device__ float  g_bmsum;
// transposed (n-major, k-contiguous), zero-padded, bf16 hi/lo weight copies
__device__ __nv_bfloat16 g_W1t_h[HH * 512];
__device__ __nv_bfloat16 g_W1t_l[HH * 512];
__device__ __nv_bfloat16 g_W2t_h[HH * 128];
__device__ __nv_bfloat16 g_W2t_l[HH * 128];

// ---------------- helpers ----------------------------------------------------
__device__ __forceinline__ uint32_t pack_bf16(float x, float y) {
    __nv_bfloat162 t;
    t.x = __float2bfloat16_rn(x);
    t.y = __float2bfloat16_rn(y);
    return *reinterpret_cast<uint32_t*>(&t);
}

__device__ __forceinline__ void mma16816(float* c, uint32_t a0, uint32_t a1,
                                         uint32_t a2, uint32_t a3,
                                         uint32_t b0, uint32_t b1) {
    asm volatile(
        "mma.sync.aligned.m16n8k16.row.col.f32.bf16.bf16.f32 "
        "{%0,%1,%2,%3}, {%4,%5,%6,%7}, {%8,%9}, {%0,%1,%2,%3};"
        : "+f"(c[0]), "+f"(c[1]), "+f"(c[2]), "+f"(c[3])
        : "r"(a0), "r"(a1), "r"(a2), "r"(a3), "r"(b0), "r"(b1));
}

// ---------------- setup kernels --------------------------------------------
__global__ void k_zero() {
    int i = blockIdx.x * blockDim.x + threadIdx.x;
    if (i < NN) { g_deg_out[i] = 0; g_deg_in[i] = 0; }
}

__global__ void k_count_out(const int* __restrict__ src) {
    int e = blockIdx.x * blockDim.x + threadIdx.x;
    if (e < EE) atomicAdd(&g_deg_out[src[e]], 1);
}

__global__ void k_count_in(const int* __restrict__ dst) {
    int e = blockIdx.x * blockDim.x + threadIdx.x;
    if (e < EE) atomicAdd(&g_deg_in[dst[e]], 1);
}

// single-block exclusive scan of g_deg_in -> g_off, copy into g_cur
__global__ void k_scan() {
    const int T  = 1024;
    const int CH = (NN + T - 1) / T;
    int t = threadIdx.x;
    int b = t * CH;
    int e = min(b + CH, NN);

    int s = 0;
    for (int i = b; i < e; i++) s += g_deg_in[i];

    int lane = t & 31, wid = t >> 5;
    int inc = s;
    #pragma unroll
    for (int o = 1; o < 32; o <<= 1) {
        int u = __shfl_up_sync(0xffffffffu, inc, o);
        if (lane >= o) inc += u;
    }
    __shared__ int wsum[32];
    if (lane == 31) wsum[wid] = inc;
    __syncthreads();
    if (wid == 0) {
        int w = wsum[lane];
        #pragma unroll
        for (int o = 1; o < 32; o <<= 1) {
            int u = __shfl_up_sync(0xffffffffu, w, o);
            if (lane >= o) w += u;
        }
        wsum[lane] = w;
    }
    __syncthreads();
    int run = inc - s + (wid ? wsum[wid - 1] : 0);

    for (int i = b; i < e; i++) {
        g_off[i] = run;
        g_cur[i] = run;
        run += g_deg_in[i];
    }
    if (b < NN && e == NN) g_off[NN] = run;
}

__global__ void k_scatter(const int* __restrict__ src, const int* __restrict__ dst) {
    int e = blockIdx.x * blockDim.x + threadIdx.x;
    if (e < EE) {
        int p = atomicAdd(&g_cur[dst[e]], 1);
        g_csr[p] = src[e];
    }
}

// weight prep: transpose/pad/split W1,W2 to bf16 hi/lo; block 0 also does wmsum
__global__ void k_wprep(const float* __restrict__ W1, const float* __restrict__ W2,
                        const float* __restrict__ Wm, const float* __restrict__ bm) {
    int idx = blockIdx.x * blockDim.x + threadIdx.x;
    if (idx < HH * 512) {
        int j = idx >> 9, k = idx & 511;
        float v = (k < FIN) ? W1[k * HH + j] : 0.f;
        __nv_bfloat16 h = __float2bfloat16_rn(v);
        g_W1t_h[idx] = h;
        g_W1t_l[idx] = __float2bfloat16_rn(v - __bfloat162float(h));
    }
    if (idx < HH * 128) {
        int j = idx >> 7, k = idx & 127;
        float v = (k < HH) ? W2[k * HH + j] : 0.f;
        __nv_bfloat16 h = __float2bfloat16_rn(v);
        g_W2t_h[idx] = h;
        g_W2t_l[idx] = __float2bfloat16_rn(v - __bfloat162float(h));
    }
    if (blockIdx.x == 0 && threadIdx.x < HH) {
        int k = threadIdx.x;
        float s = 0.f;
        for (int j = 0; j < HH; j++) s += Wm[k * HH + j];
        g_wmsum[k] = s;
        if (k == 0) {
            float sb = 0.f;
            for (int j = 0; j < HH; j++) sb += bm[j];
            g_bmsum = sb;
        }
    }
}

// ---------------- tensor-core GEMM via mma.sync, double-buffered ------------
// CTA: 128 rows x 96 cols, 8 warps as 4(m) x 2(n); warp = 2 m16 bands x 6 n8.
// K chunks of 32 (2 x k16). bf16 hi/lo 3-pass: AhBh + AhBl + AlBh.
#define AB_U32 2176              // 128*17
#define BB_U32 1632              // 96*17
#define GEMM_SMEM ((4 * AB_U32 + 4 * BB_U32) * 4)   // 60928 bytes

template <int KCHUNKS, int KREAL, int LDA, int WLD, int NROWS, bool HALF_IN>
__global__ void __launch_bounds__(256, 2)
k_gemm_mma(const void* __restrict__ Ain,
           const __nv_bfloat16* __restrict__ Wh,
           const __nv_bfloat16* __restrict__ Wl,
           __half* __restrict__ C) {
    extern __shared__ uint32_t dyn[];
    uint32_t* const AhB[2] = { dyn,               dyn + 2 * AB_U32 };
    uint32_t* const AlB[2] = { dyn + AB_U32,      dyn + 3 * AB_U32 };
    uint32_t* const bbase  = dyn + 4 * AB_U32;
    uint32_t* const BhB[2] = { bbase,             bbase + 2 * BB_U32 };
    uint32_t* const BlB[2] = { bbase + BB_U32,    bbase + 3 * BB_U32 };

    int tid = threadIdx.x, wid = tid >> 5, lane = tid & 31;
    int mw = wid >> 1, nw = wid & 1;
    int r0 = blockIdx.x * 128;

    float acc[2][6][4];
    #pragma unroll
    for (int b = 0; b < 2; b++)
        #pragma unroll
        for (int t = 0; t < 6; t++)
            #pragma unroll
            for (int j = 0; j < 4; j++) acc[b][t][j] = 0.f;

    const int qr = lane >> 2, qc = lane & 3;

    float2   va[8];
    uint32_t vbh[6], vbl[6];

    #define LOAD_CHUNK(cc)                                                     \
    {                                                                          \
        int kbase = (cc) * 32;                                                 \
        int kvp = (KREAL - kbase) >> 1;                                        \
        if (kvp > 16) kvp = 16;                                                \
        _Pragma("unroll")                                                      \
        for (int it = 0; it < 8; it++) {                                       \
            int idx = tid + it * 256;                                          \
            int r = idx >> 4, kp = idx & 15;                                   \
            int gr = r0 + r;                                                   \
            float2 v = make_float2(0.f, 0.f);                                  \
            if (gr < NROWS && kp < kvp) {                                      \
                if (HALF_IN) {                                                 \
                    __half2 h2 = *(const __half2*)((const __half*)Ain +        \
                                   (size_t)gr * LDA + kbase + 2 * kp);         \
                    v = __half22float2(h2);                                    \
                } else {                                                       \
                    v = *(const float2*)((const float*)Ain +                   \
                                   (size_t)gr * LDA + kbase + 2 * kp);         \
                }                                                              \
            }                                                                  \
            va[it] = v;                                                        \
        }                                                                      \
        _Pragma("unroll")                                                      \
        for (int it = 0; it < 6; it++) {                                       \
            int idx = tid + it * 256;                                          \
            int n = idx >> 4, kp = idx & 15;                                   \
            vbh[it] = *(const uint32_t*)(Wh + (size_t)n * WLD + kbase + 2 * kp);\
            vbl[it] = *(const uint32_t*)(Wl + (size_t)n * WLD + kbase + 2 * kp);\
        }                                                                      \
    }

    #define STORE_CHUNK(buf)                                                   \
    {                                                                          \
        _Pragma("unroll")                                                      \
        for (int it = 0; it < 8; it++) {                                       \
            int idx = tid + it * 256;                                          \
            int r = idx >> 4, kp = idx & 15;                                   \
            float2 v = va[it];                                                 \
            float hx = __bfloat162float(__float2bfloat16_rn(v.x));             \
            float hy = __bfloat162float(__float2bfloat16_rn(v.y));             \
            AhB[buf][r * 17 + kp] = pack_bf16(v.x, v.y);                       \
            AlB[buf][r * 17 + kp] = pack_bf16(v.x - hx, v.y - hy);             \
        }                                                                      \
        _Pragma("unroll")                                                      \
        for (int it = 0; it < 6; it++) {                                       \
            int idx = tid + it * 256;                                          \
            int n = idx >> 4, kp = idx & 15;                                   \
            BhB[buf][n * 17 + kp] = vbh[it];                                   \
            BlB[buf][n * 17 + kp] = vbl[it];                                   \
        }                                                                      \
    }

    LOAD_CHUNK(0);
    STORE_CHUNK(0);
    __syncthreads();

    for (int c = 0; c < KCHUNKS; c++) {
        if (c + 1 < KCHUNKS) LOAD_CHUNK(c + 1);

        const uint32_t* sAh = AhB[c & 1];
        const uint32_t* sAl = AlB[c & 1];
        const uint32_t* sBh = BhB[c & 1];
        const uint32_t* sBl = BlB[c & 1];

        #pragma unroll
        for (int s = 0; s < 2; s++) {
            int kq = s * 8 + qc;
            uint32_t bh[6][2], bl[6][2];
            #pragma unroll
            for (int t = 0; t < 6; t++) {
                int bc = nw * 48 + t * 8 + qr;
                bh[t][0] = sBh[bc * 17 + kq]; bh[t][1] = sBh[bc * 17 + kq + 4];
                bl[t][0] = sBl[bc * 17 + kq]; bl[t][1] = sBl[bc * 17 + kq + 4];
            }
            #pragma unroll
            for (int b = 0; b < 2; b++) {
                int ar = mw * 32 + b * 16 + qr;
                uint32_t ah0 = sAh[ar * 17 + kq],       ah1 = sAh[(ar + 8) * 17 + kq];
                uint32_t ah2 = sAh[ar * 17 + kq + 4],   ah3 = sAh[(ar + 8) * 17 + kq + 4];
                uint32_t al0 = sAl[ar * 17 + kq],       al1 = sAl[(ar + 8) * 17 + kq];
                uint32_t al2 = sAl[ar * 17 + kq + 4],   al3 = sAl[(ar + 8) * 17 + kq + 4];
                #pragma unroll
                for (int t = 0; t < 6; t++) {
                    mma16816(acc[b][t], ah0, ah1, ah2, ah3, bh[t][0], bh[t][1]);
                    mma16816(acc[b][t], ah0, ah1, ah2, ah3, bl[t][0], bl[t][1]);
                    mma16816(acc[b][t], al0, al1, al2, al3, bh[t][0], bh[t][1]);
                }
            }
        }

        if (c + 1 < KCHUNKS) {
            STORE_CHUNK((c + 1) & 1);
            __syncthreads();
        }
    }

    #pragma unroll
    for (int b = 0; b < 2; b++) {
        int gr = r0 + mw * 32 + b * 16 + qr;
        #pragma unroll
        for (int t = 0; t < 6; t++) {
            int col = nw * 48 + t * 8 + 2 * qc;
            #pragma unroll
            for (int h = 0; h < 2; h++) {
                int row = gr + h * 8;
                if (row < NROWS)
                    *(__half2*)(C + (size_t)row * HH + col) =
                        __floats2half2_rn(acc[b][t][2 * h], acc[b][t][2 * h + 1]);
            }
        }
    }
    #undef LOAD_CHUNK
    #undef STORE_CHUNK
}

// ---------------- Y01 fill (both views): no[n]*Yplain[n] | no[n]*Yplain[perm[n]]
__global__ void k_permscale2(const int* __restrict__ perm) {
    int n = (blockIdx.x * blockDim.x + threadIdx.x) >> 5;
    if (n >= NN) return;
    int lane = threadIdx.x & 31;
    int view = lane >> 4, chunk = lane & 15;
    if (chunk >= 12) return;
    int r = view ? perm[n] : n;
    float no = rsqrtf((float)max(g_deg_out[n], 1));
    uint4 v = *(const uint4*)(g_Yplain + (size_t)r * HH + chunk * 8);
    __half2* h2 = (__half2*)&v;
    uint4 o;
    __half2* oh = (__half2*)&o;
    #pragma unroll
    for (int t = 0; t < 4; t++) {
        float2 f = __half22float2(h2[t]);
        oh[t] = __floats2half2_rn(no * f.x, no * f.y);
    }
    *(uint4*)(g_Y01 + (size_t)n * (2 * HH) + (size_t)view * HH + chunk * 8) = o;
}

// ---------------- SpMM gather core: 4x unrolled, 16B/lane -------------------
__device__ __forceinline__ void spmm_gather(const __half* __restrict__ base,
                                            size_t loff, int b, int e, bool act,
                                            float* acc) {
    #pragma unroll
    for (int t = 0; t < 8; t++) acc[t] = 0.f;
    auto addv = [&](uint4 v) {
        __half2* h2 = (__half2*)&v;
        #pragma unroll
        for (int t = 0; t < 4; t++) {
            float2 f = __half22float2(h2[t]);
            acc[2 * t]     += f.x;
            acc[2 * t + 1] += f.y;
        }
    };
    int p = b;
    for (; p + 4 <= e; p += 4) {
        int s0 = g_csr[p], s1 = g_csr[p + 1], s2 = g_csr[p + 2], s3 = g_csr[p + 3];
        if (act) {
            uint4 v0 = *(const uint4*)(base + (size_t)s0 * (2 * HH) + loff);
            uint4 v1 = *(const uint4*)(base + (size_t)s1 * (2 * HH) + loff);
            uint4 v2 = *(const uint4*)(base + (size_t)s2 * (2 * HH) + loff);
            uint4 v3 = *(const uint4*)(base + (size_t)s3 * (2 * HH) + loff);
            addv(v0); addv(v1); addv(v2); addv(v3);
        }
    }
    for (; p < e; p++) {
        int s = g_csr[p];
        if (act) addv(*(const uint4*)(base + (size_t)s * (2 * HH) + loff));
    }
}

// ---------------- fused SpMM layer 1: thread = (node, 24-chunk) -------------
// blockDim 384 = 16 nodes/block; no cross-thread communication needed.
__global__ void __launch_bounds__(384)
k_spmm1(const float* __restrict__ b1, const float* __restrict__ a1) {
    __shared__ float sb1[HH], sa1[HH];
    for (int j = threadIdx.x; j < HH; j += blockDim.x) {
        sb1[j] = b1[j];
        sa1[j] = a1[j];
    }
    __syncthreads();

    int t = blockIdx.x * 384 + threadIdx.x;
    int n = t / 24, c = t - n * 24;
    if (n >= NN) return;
    int view = c / 12, chunk = c - view * 12;
    int b = g_off[n], e = g_off[n + 1];

    float acc[8];
    spmm_gather(g_Y01, (size_t)view * HH + chunk * 8, b, e, true, acc);

    float nin  = rsqrtf((float)max(g_deg_in[n], 1));
    float nout = rsqrtf((float)max(g_deg_out[n], 1));
    uint4 o;
    __half2* oh = (__half2*)&o;
    #pragma unroll
    for (int q = 0; q < 4; q++) {
        float r[2];
        #pragma unroll
        for (int u = 0; u < 2; u++) {
            int j = chunk * 8 + 2 * q + u;
            float h = fmaf(acc[2 * q + u], nin, sb1[j]);
            h = (h >= 0.f) ? h : sa1[j] * h;
            r[u] = nout * h;
        }
        oh[q] = __floats2half2_rn(r[0], r[1]);
    }
    *(uint4*)(g_B0h + ((size_t)(2 * n + view)) * HH + chunk * 8) = o;
}

// ---------------- fused SpMM layer 2 + readout, both views ------------------
__global__ void k_spmm2(const float* __restrict__ b2, const float* __restrict__ a2,
                        float* __restrict__ out) {
    __shared__ float sb2[HH], sa2[HH], swm[HH];
    for (int j = threadIdx.x; j < HH; j += blockDim.x) {
        sb2[j] = b2[j];
        sa2[j] = a2[j];
        swm[j] = g_wmsum[j];
    }
    __syncthreads();

    int n = (blockIdx.x * blockDim.x + threadIdx.x) >> 5;
    if (n >= NN) return;
    int lane = threadIdx.x & 31;
    int view = lane >> 4, chunk = lane & 15;
    bool act = chunk < 12;
    int b = g_off[n], e = g_off[n + 1];

    float acc[8];
    spmm_gather(g_B2h, (size_t)view * HH + chunk * 8, b, e, act, acc);

    float part = 0.f;
    if (act) {
        float nin = rsqrtf((float)max(g_deg_in[n], 1));
        #pragma unroll
        for (int t = 0; t < 8; t++) {
            int j = chunk * 8 + t;
            float h = fmaf(acc[t], nin, sb2[j]);
            h = (h >= 0.f) ? h : sa2[j] * h;
            part = fmaf(h, swm[j], part);
        }
    }
    #pragma unroll
    for (int o = 8; o; o >>= 1)
        part += __shfl_down_sync(0xffffffffu, part, o, 16);
    if (chunk == 0) out[(size_t)view * NN + n] = part + g_bmsum;
}

// ---------------- launch ----------------------------------------------------
extern "C" void kernel_launch(void* const* d_in, const int* in_sizes, int n_in,
                              void* d_out, int out_size) {
    const float* x    = (const float*)d_in[0];
    const int*   src  = (const int*)  d_in[1];
    const int*   dst  = (const int*)  d_in[2];
    const int*   perm = (const int*)  d_in[3];
    const float* W1   = (const float*)d_in[4];
    const float* b1   = (const float*)d_in[5];
    const float* a1   = (const float*)d_in[6];
    const float* W2   = (const float*)d_in[7];
    const float* b2   = (const float*)d_in[8];
    const float* a2   = (const float*)d_in[9];
    const float* Wm   = (const float*)d_in[10];
    const float* bm   = (const float*)d_in[11];
    float* out = (float*)d_out;

    __half *pYp, *pB0h, *pB2h;
    __nv_bfloat16 *pW1h, *pW1l, *pW2h, *pW2l;
    cudaGetSymbolAddress((void**)&pYp,  g_Yplain);
    cudaGetSymbolAddress((void**)&pB0h, g_B0h);
    cudaGetSymbolAddress((void**)&pB2h, g_B2h);
    cudaGetSymbolAddress((void**)&pW1h, g_W1t_h);
    cudaGetSymbolAddress((void**)&pW1l, g_W1t_l);
    cudaGetSymbolAddress((void**)&pW2h, g_W2t_h);
    cudaGetSymbolAddress((void**)&pW2l, g_W2t_l);

    static cudaStream_t sB = nullptr, sC = nullptr;
    static cudaEvent_t evF = nullptr, evZ = nullptr, evCSR = nullptr, evDeg = nullptr;
    if (!sB) {
        cudaStreamCreateWithFlags(&sB, cudaStreamNonBlocking);
        cudaStreamCreateWithFlags(&sC, cudaStreamNonBlocking);
        cudaEventCreateWithFlags(&evF,   cudaEventDisableTiming);
        cudaEventCreateWithFlags(&evZ,   cudaEventDisableTiming);
        cudaEventCreateWithFlags(&evCSR, cudaEventDisableTiming);
        cudaEventCreateWithFlags(&evDeg, cudaEventDisableTiming);
        cudaFuncSetAttribute(k_gemm_mma<16, FIN, FIN, 512, NN, false>,
                             cudaFuncAttributeMaxDynamicSharedMemorySize, GEMM_SMEM);
        cudaFuncSetAttribute(k_gemm_mma<3, HH, HH, 128, 2 * NN, true>,
                             cudaFuncAttributeMaxDynamicSharedMemorySize, GEMM_SMEM);
    }

    const int GN  = (NN + 255) / 256;
    const int GE  = (EE + 255) / 256;
    const int GW  = (NN * 32 + 255) / 256;           // warp-per-node
    const int GS1 = (NN * 24 + 383) / 384;           // spmm1 groups
    const int GT1 = (NN + 127) / 128;
    const int GT2 = (2 * NN + 127) / 128;

    // fork point
    cudaEventRecord(evF, 0);
    cudaStreamWaitEvent(sB, evF, 0);
    cudaStreamWaitEvent(sC, evF, 0);

    // (1) main: weight prep (GEMM1's only dependency)
    k_wprep<<<(HH * 512 + 255) / 256, 256>>>(W1, W2, Wm, bm);

    // (2-5) side B: zero degs -> count_in -> scan -> scatter
    k_zero<<<GN, 256, 0, sB>>>();
    cudaEventRecord(evZ, sB);
    k_count_in<<<GE, 256, 0, sB>>>(dst);
    k_scan<<<1, 1024, 0, sB>>>();
    k_scatter<<<GE, 256, 0, sB>>>(src, dst);
    cudaEventRecord(evCSR, sB);

    // (6) main: GEMM1 (profiled launch), no degree dependency
    k_gemm_mma<16, FIN, FIN, 512, NN, false>
        <<<GT1, 256, GEMM_SMEM>>>(x, pW1h, pW1l, pYp);

    // (7) side C: count_out, hidden under GEMM1
    cudaStreamWaitEvent(sC, evZ, 0);
    k_count_out<<<GE, 256, 0, sC>>>(src);
    cudaEventRecord(evDeg, sC);

    // (8) main: scale both views (needs deg_out + Yplain)
    cudaStreamWaitEvent(0, evDeg, 0);
    k_permscale2<<<GW, 256>>>(perm);

    // (9-11) main: spmm1 -> GEMM2 -> spmm2
    cudaStreamWaitEvent(0, evCSR, 0);
    k_spmm1<<<GS1, 384>>>(b1, a1);
    k_gemm_mma<3, HH, HH, 128, 2 * NN, true>
        <<<GT2, 256, GEMM_SMEM>>>(pB0h, pW2h, pW2l, pB2h);
    k_spmm2<<<GW, 256>>>(b2, a2, out);
}

// round 9
// speedup vs baseline: 2.3182x; 1.0701x over previous
#include <cuda_runtime.h>
#include <cuda_bf16.h>
#include <cuda_fp16.h>
#include <cstdint>

#define NN 50000
#define EE 800000
#define FIN 500
#define HH 96
#define NB 196        // scan blocks: ceil(NN/256)

// ---------------- scratch (device globals; no allocation allowed) ----------
__device__ int    g_deg_out[NN];
__device__ int    g_deg_in[NN];
__device__ int    g_off[NN + 1];
__device__ int    g_cur[NN];
__device__ int    g_bsum[NB];
__device__ int    g_boff[NB];
__device__ int    g_csr[EE];             // src per CSR slot
__device__ __half g_Yplain[NN * HH];     // x @ W1, fp16
__device__ __half g_Y01[NN * 2 * HH];    // [norm_out*Y | norm_out*Y[perm]] per node
__device__ __half g_B0h[2 * NN * HH];    // layer-1 out, row n=2i+v, fp16
__device__ __half g_B2h[2 * NN * HH];    // B0 @ W2, row n=2i+v, fp16
__device__ float  g_wmsum[HH];
__device__ float  g_bmsum;
// transposed (n-major, k-contiguous), zero-padded, bf16 hi/lo weight copies
__device__ __nv_bfloat16 g_W1t_h[HH * 512];
__device__ __nv_bfloat16 g_W1t_l[HH * 512];
__device__ __nv_bfloat16 g_W2t_h[HH * 128];
__device__ __nv_bfloat16 g_W2t_l[HH * 128];

// ---------------- helpers ----------------------------------------------------
__device__ __forceinline__ uint32_t pack_bf16(float x, float y) {
    __nv_bfloat162 t;
    t.x = __float2bfloat16_rn(x);
    t.y = __float2bfloat16_rn(y);
    return *reinterpret_cast<uint32_t*>(&t);
}

__device__ __forceinline__ void mma16816(float* c, uint32_t a0, uint32_t a1,
                                         uint32_t a2, uint32_t a3,
                                         uint32_t b0, uint32_t b1) {
    asm volatile(
        "mma.sync.aligned.m16n8k16.row.col.f32.bf16.bf16.f32 "
        "{%0,%1,%2,%3}, {%4,%5,%6,%7}, {%8,%9}, {%0,%1,%2,%3};"
        : "+f"(c[0]), "+f"(c[1]), "+f"(c[2]), "+f"(c[3])
        : "r"(a0), "r"(a1), "r"(a2), "r"(a3), "r"(b0), "r"(b1));
}

// 256-thread block inclusive scan; returns inclusive, fills total via shared
__device__ __forceinline__ int block_scan256(int v, int tid) {
    int lane = tid & 31, wid = tid >> 5;
    int inc = v;
    #pragma unroll
    for (int o = 1; o < 32; o <<= 1) {
        int u = __shfl_up_sync(0xffffffffu, inc, o);
        if (lane >= o) inc += u;
    }
    __shared__ int ws[8];
    if (lane == 31) ws[wid] = inc;
    __syncthreads();
    if (wid == 0) {
        int w = (lane < 8) ? ws[lane] : 0;
        #pragma unroll
        for (int o = 1; o < 8; o <<= 1) {
            int u = __shfl_up_sync(0xffffffffu, w, o);
            if (lane >= o) w += u;
        }
        if (lane < 8) ws[lane] = w;
    }
    __syncthreads();
    return inc + (wid ? ws[wid - 1] : 0);
}

// ---------------- setup kernels --------------------------------------------
__global__ void k_zero() {
    int i = blockIdx.x * blockDim.x + threadIdx.x;
    if (i < NN) { g_deg_out[i] = 0; g_deg_in[i] = 0; }
}

__global__ void k_count_out(const int* __restrict__ src) {
    int e = blockIdx.x * blockDim.x + threadIdx.x;
    if (e < EE) atomicAdd(&g_deg_out[src[e]], 1);
}

__global__ void k_count_in(const int* __restrict__ dst) {
    int e = blockIdx.x * blockDim.x + threadIdx.x;
    if (e < EE) atomicAdd(&g_deg_in[dst[e]], 1);
}

// ---- multi-block exclusive scan of g_deg_in -> g_off (3 phases) -----------
__global__ void k_scan_a() {
    int tid = threadIdx.x;
    int i = blockIdx.x * 256 + tid;
    int v = (i < NN) ? g_deg_in[i] : 0;
    // warp reduce then block reduce
    #pragma unroll
    for (int o = 16; o; o >>= 1) v += __shfl_down_sync(0xffffffffu, v, o);
    __shared__ int ws[8];
    if ((tid & 31) == 0) ws[tid >> 5] = v;
    __syncthreads();
    if (tid < 8) {
        int s = ws[tid];
        #pragma unroll
        for (int o = 4; o; o >>= 1) s += __shfl_down_sync(0xffu, s, o);
        if (tid == 0) g_bsum[blockIdx.x] = s;
    }
}

__global__ void k_scan_b() {
    int tid = threadIdx.x;
    int v = (tid < NB) ? g_bsum[tid] : 0;
    int inc = block_scan256(v, tid);
    if (tid < NB) g_boff[tid] = inc - v;
    if (tid == 0) g_off[NN] = EE;
}

__global__ void k_scan_c() {
    int tid = threadIdx.x;
    int i = blockIdx.x * 256 + tid;
    int v = (i < NN) ? g_deg_in[i] : 0;
    int inc = block_scan256(v, tid);
    int run = g_boff[blockIdx.x] + inc - v;
    if (i < NN) { g_off[i] = run; g_cur[i] = run; }
}

__global__ void k_scatter(const int* __restrict__ src, const int* __restrict__ dst) {
    int e = blockIdx.x * blockDim.x + threadIdx.x;
    if (e < EE) {
        int p = atomicAdd(&g_cur[dst[e]], 1);
        g_csr[p] = src[e];
    }
}

// weight prep: transpose/pad/split W1,W2 to bf16 hi/lo; block 0 also does wmsum
__global__ void k_wprep(const float* __restrict__ W1, const float* __restrict__ W2,
                        const float* __restrict__ Wm, const float* __restrict__ bm) {
    int idx = blockIdx.x * blockDim.x + threadIdx.x;
    if (idx < HH * 512) {
        int j = idx >> 9, k = idx & 511;
        float v = (k < FIN) ? W1[k * HH + j] : 0.f;
        __nv_bfloat16 h = __float2bfloat16_rn(v);
        g_W1t_h[idx] = h;
        g_W1t_l[idx] = __float2bfloat16_rn(v - __bfloat162float(h));
    }
    if (idx < HH * 128) {
        int j = idx >> 7, k = idx & 127;
        float v = (k < HH) ? W2[k * HH + j] : 0.f;
        __nv_bfloat16 h = __float2bfloat16_rn(v);
        g_W2t_h[idx] = h;
        g_W2t_l[idx] = __float2bfloat16_rn(v - __bfloat162float(h));
    }
    if (blockIdx.x == 0 && threadIdx.x < HH) {
        int k = threadIdx.x;
        float s = 0.f;
        for (int j = 0; j < HH; j++) s += Wm[k * HH + j];
        g_wmsum[k] = s;
        if (k == 0) {
            float sb = 0.f;
            for (int j = 0; j < HH; j++) sb += bm[j];
            g_bmsum = sb;
        }
    }
}

// ---------------- tensor-core GEMM via mma.sync, double-buffered ------------
#define AB_U32 2176              // 128*17
#define BB_U32 1632              // 96*17
#define GEMM_SMEM ((4 * AB_U32 + 4 * BB_U32) * 4)   // 60928 bytes

template <int KCHUNKS, int KREAL, int LDA, int WLD, int NROWS, bool HALF_IN>
__global__ void __launch_bounds__(256, 2)
k_gemm_mma(const void* __restrict__ Ain,
           const __nv_bfloat16* __restrict__ Wh,
           const __nv_bfloat16* __restrict__ Wl,
           __half* __restrict__ C) {
    extern __shared__ uint32_t dyn[];
    uint32_t* const AhB[2] = { dyn,               dyn + 2 * AB_U32 };
    uint32_t* const AlB[2] = { dyn + AB_U32,      dyn + 3 * AB_U32 };
    uint32_t* const bbase  = dyn + 4 * AB_U32;
    uint32_t* const BhB[2] = { bbase,             bbase + 2 * BB_U32 };
    uint32_t* const BlB[2] = { bbase + BB_U32,    bbase + 3 * BB_U32 };

    int tid = threadIdx.x, wid = tid >> 5, lane = tid & 31;
    int mw = wid >> 1, nw = wid & 1;
    int r0 = blockIdx.x * 128;

    float acc[2][6][4];
    #pragma unroll
    for (int b = 0; b < 2; b++)
        #pragma unroll
        for (int t = 0; t < 6; t++)
            #pragma unroll
            for (int j = 0; j < 4; j++) acc[b][t][j] = 0.f;

    const int qr = lane >> 2, qc = lane & 3;

    float2   va[8];
    uint32_t vbh[6], vbl[6];

    #define LOAD_CHUNK(cc)                                                     \
    {                                                                          \
        int kbase = (cc) * 32;                                                 \
        int kvp = (KREAL - kbase) >> 1;                                        \
        if (kvp > 16) kvp = 16;                                                \
        _Pragma("unroll")                                                      \
        for (int it = 0; it < 8; it++) {                                       \
            int idx = tid + it * 256;                                          \
            int r = idx >> 4, kp = idx & 15;                                   \
            int gr = r0 + r;                                                   \
            float2 v = make_float2(0.f, 0.f);                                  \
            if (gr < NROWS && kp < kvp) {                                      \
                if (HALF_IN) {                                                 \
                    __half2 h2 = *(const __half2*)((const __half*)Ain +        \
                                   (size_t)gr * LDA + kbase + 2 * kp);         \
                    v = __half22float2(h2);                                    \
                } else {                                                       \
                    v = *(const float2*)((const float*)Ain +                   \
                                   (size_t)gr * LDA + kbase + 2 * kp);         \
                }                                                              \
            }                                                                  \
            va[it] = v;                                                        \
        }                                                                      \
        _Pragma("unroll")                                                      \
        for (int it = 0; it < 6; it++) {                                       \
            int idx = tid + it * 256;                                          \
            int n = idx >> 4, kp = idx & 15;                                   \
            vbh[it] = *(const uint32_t*)(Wh + (size_t)n * WLD + kbase + 2 * kp);\
            vbl[it] = *(const uint32_t*)(Wl + (size_t)n * WLD + kbase + 2 * kp);\
        }                                                                      \
    }

    #define STORE_CHUNK(buf)                                                   \
    {                                                                          \
        _Pragma("unroll")                                                      \
        for (int it = 0; it < 8; it++) {                                       \
            int idx = tid + it * 256;                                          \
            int r = idx >> 4, kp = idx & 15;                                   \
            float2 v = va[it];                                                 \
            float hx = __bfloat162float(__float2bfloat16_rn(v.x));             \
            float hy = __bfloat162float(__float2bfloat16_rn(v.y));             \
            AhB[buf][r * 17 + kp] = pack_bf16(v.x, v.y);                       \
            AlB[buf][r * 17 + kp] = pack_bf16(v.x - hx, v.y - hy);             \
        }                                                                      \
        _Pragma("unroll")                                                      \
        for (int it = 0; it < 6; it++) {                                       \
            int idx = tid + it * 256;                                          \
            int n = idx >> 4, kp = idx & 15;                                   \
            BhB[buf][n * 17 + kp] = vbh[it];                                   \
            BlB[buf][n * 17 + kp] = vbl[it];                                   \
        }                                                                      \
    }

    LOAD_CHUNK(0);
    STORE_CHUNK(0);
    __syncthreads();

    for (int c = 0; c < KCHUNKS; c++) {
        if (c + 1 < KCHUNKS) LOAD_CHUNK(c + 1);

        const uint32_t* sAh = AhB[c & 1];
        const uint32_t* sAl = AlB[c & 1];
        const uint32_t* sBh = BhB[c & 1];
        const uint32_t* sBl = BlB[c & 1];

        #pragma unroll
        for (int s = 0; s < 2; s++) {
            int kq = s * 8 + qc;
            uint32_t bh[6][2], bl[6][2];
            #pragma unroll
            for (int t = 0; t < 6; t++) {
                int bc = nw * 48 + t * 8 + qr;
                bh[t][0] = sBh[bc * 17 + kq]; bh[t][1] = sBh[bc * 17 + kq + 4];
                bl[t][0] = sBl[bc * 17 + kq]; bl[t][1] = sBl[bc * 17 + kq + 4];
            }
            #pragma unroll
            for (int b = 0; b < 2; b++) {
                int ar = mw * 32 + b * 16 + qr;
                uint32_t ah0 = sAh[ar * 17 + kq],       ah1 = sAh[(ar + 8) * 17 + kq];
                uint32_t ah2 = sAh[ar * 17 + kq + 4],   ah3 = sAh[(ar + 8) * 17 + kq + 4];
                uint32_t al0 = sAl[ar * 17 + kq],       al1 = sAl[(ar + 8) * 17 + kq];
                uint32_t al2 = sAl[ar * 17 + kq + 4],   al3 = sAl[(ar + 8) * 17 + kq + 4];
                #pragma unroll
                for (int t = 0; t < 6; t++) {
                    mma16816(acc[b][t], ah0, ah1, ah2, ah3, bh[t][0], bh[t][1]);
                    mma16816(acc[b][t], ah0, ah1, ah2, ah3, bl[t][0], bl[t][1]);
                    mma16816(acc[b][t], al0, al1, al2, al3, bh[t][0], bh[t][1]);
                }
            }
        }

        if (c + 1 < KCHUNKS) {
            STORE_CHUNK((c + 1) & 1);
            __syncthreads();
        }
    }

    #pragma unroll
    for (int b = 0; b < 2; b++) {
        int gr = r0 + mw * 32 + b * 16 + qr;
        #pragma unroll
        for (int t = 0; t < 6; t++) {
            int col = nw * 48 + t * 8 + 2 * qc;
            #pragma unroll
            for (int h = 0; h < 2; h++) {
                int row = gr + h * 8;
                if (row < NROWS)
                    *(__half2*)(C + (size_t)row * HH + col) =
                        __floats2half2_rn(acc[b][t][2 * h], acc[b][t][2 * h + 1]);
            }
        }
    }
    #undef LOAD_CHUNK
    #undef STORE_CHUNK
}

// ---------------- Y01 fill (both views): no[n]*Yplain[n] | no[n]*Yplain[perm[n]]
__global__ void k_permscale2(const int* __restrict__ perm) {
    int n = (blockIdx.x * blockDim.x + threadIdx.x) >> 5;
    if (n >= NN) return;
    int lane = threadIdx.x & 31;
    int view = lane >> 4, chunk = lane & 15;
    if (chunk >= 12) return;
    int r = view ? perm[n] : n;
    float no = rsqrtf((float)max(g_deg_out[n], 1));
    uint4 v = *(const uint4*)(g_Yplain + (size_t)r * HH + chunk * 8);
    __half2* h2 = (__half2*)&v;
    uint4 o;
    __half2* oh = (__half2*)&o;
    #pragma unroll
    for (int t = 0; t < 4; t++) {
        float2 f = __half22float2(h2[t]);
        oh[t] = __floats2half2_rn(no * f.x, no * f.y);
    }
    *(uint4*)(g_Y01 + (size_t)n * (2 * HH) + (size_t)view * HH + chunk * 8) = o;
}

// ---------------- SpMM gather core: 4x unrolled, 16B/lane -------------------
__device__ __forceinline__ void spmm_gather(const __half* __restrict__ base,
                                            size_t loff, int b, int e, bool act,
                                            float* acc) {
    #pragma unroll
    for (int t = 0; t < 8; t++) acc[t] = 0.f;
    auto addv = [&](uint4 v) {
        __half2* h2 = (__half2*)&v;
        #pragma unroll
        for (int t = 0; t < 4; t++) {
            float2 f = __half22float2(h2[t]);
            acc[2 * t]     += f.x;
            acc[2 * t + 1] += f.y;
        }
    };
    int p = b;
    for (; p + 4 <= e; p += 4) {
        int s0 = g_csr[p], s1 = g_csr[p + 1], s2 = g_csr[p + 2], s3 = g_csr[p + 3];
        if (act) {
            uint4 v0 = *(const uint4*)(base + (size_t)s0 * (2 * HH) + loff);
            uint4 v1 = *(const uint4*)(base + (size_t)s1 * (2 * HH) + loff);
            uint4 v2 = *(const uint4*)(base + (size_t)s2 * (2 * HH) + loff);
            uint4 v3 = *(const uint4*)(base + (size_t)s3 * (2 * HH) + loff);
            addv(v0); addv(v1); addv(v2); addv(v3);
        }
    }
    for (; p < e; p++) {
        int s = g_csr[p];
        if (act) addv(*(const uint4*)(base + (size_t)s * (2 * HH) + loff));
    }
}

// ---------------- fused SpMM layer 1: thread = (node, 24-chunk) -------------
__global__ void __launch_bounds__(384)
k_spmm1(const float* __restrict__ b1, const float* __restrict__ a1) {
    __shared__ float sb1[HH], sa1[HH];
    for (int j = threadIdx.x; j < HH; j += blockDim.x) {
        sb1[j] = b1[j];
        sa1[j] = a1[j];
    }
    __syncthreads();

    int t = blockIdx.x * 384 + threadIdx.x;
    int n = t / 24, c = t - n * 24;
    if (n >= NN) return;
    int view = c / 12, chunk = c - view * 12;
    int b = g_off[n], e = g_off[n + 1];

    float acc[8];
    spmm_gather(g_Y01, (size_t)view * HH + chunk * 8, b, e, true, acc);

    float nin  = rsqrtf((float)max(g_deg_in[n], 1));
    float nout = rsqrtf((float)max(g_deg_out[n], 1));
    uint4 o;
    __half2* oh = (__half2*)&o;
    #pragma unroll
    for (int q = 0; q < 4; q++) {
        float r[2];
        #pragma unroll
        for (int u = 0; u < 2; u++) {
            int j = chunk * 8 + 2 * q + u;
            float h = fmaf(acc[2 * q + u], nin, sb1[j]);
            h = (h >= 0.f) ? h : sa1[j] * h;
            r[u] = nout * h;
        }
        oh[q] = __floats2half2_rn(r[0], r[1]);
    }
    *(uint4*)(g_B0h + ((size_t)(2 * n + view)) * HH + chunk * 8) = o;
}

// ---------------- fused SpMM layer 2 + readout, both views ------------------
__global__ void k_spmm2(const float* __restrict__ b2, const float* __restrict__ a2,
                        float* __restrict__ out) {
    __shared__ float sb2[HH], sa2[HH], swm[HH];
    for (int j = threadIdx.x; j < HH; j += blockDim.x) {
        sb2[j] = b2[j];
        sa2[j] = a2[j];
        swm[j] = g_wmsum[j];
    }
    __syncthreads();

    int n = (blockIdx.x * blockDim.x + threadIdx.x) >> 5;
    if (n >= NN) return;
    int lane = threadIdx.x & 31;
    int view = lane >> 4, chunk = lane & 15;
    bool act = chunk < 12;
    int b = g_off[n], e = g_off[n + 1];

    float acc[8];
    spmm_gather(g_B2h, (size_t)view * HH + chunk * 8, b, e, act, acc);

    float part = 0.f;
    if (act) {
        float nin = rsqrtf((float)max(g_deg_in[n], 1));
        #pragma unroll
        for (int t = 0; t < 8; t++) {
            int j = chunk * 8 + t;
            float h = fmaf(acc[t], nin, sb2[j]);
            h = (h >= 0.f) ? h : sa2[j] * h;
            part = fmaf(h, swm[j], part);
        }
    }
    #pragma unroll
    for (int o = 8; o; o >>= 1)
        part += __shfl_down_sync(0xffffffffu, part, o, 16);
    if (chunk == 0) out[(size_t)view * NN + n] = part + g_bmsum;
}

// ---------------- launch ----------------------------------------------------
extern "C" void kernel_launch(void* const* d_in, const int* in_sizes, int n_in,
                              void* d_out, int out_size) {
    const float* x    = (const float*)d_in[0];
    const int*   src  = (const int*)  d_in[1];
    const int*   dst  = (const int*)  d_in[2];
    const int*   perm = (const int*)  d_in[3];
    const float* W1   = (const float*)d_in[4];
    const float* b1   = (const float*)d_in[5];
    const float* a1   = (const float*)d_in[6];
    const float* W2   = (const float*)d_in[7];
    const float* b2   = (const float*)d_in[8];
    const float* a2   = (const float*)d_in[9];
    const float* Wm   = (const float*)d_in[10];
    const float* bm   = (const float*)d_in[11];
    float* out = (float*)d_out;

    __half *pYp, *pB0h, *pB2h;
    __nv_bfloat16 *pW1h, *pW1l, *pW2h, *pW2l;
    cudaGetSymbolAddress((void**)&pYp,  g_Yplain);
    cudaGetSymbolAddress((void**)&pB0h, g_B0h);
    cudaGetSymbolAddress((void**)&pB2h, g_B2h);
    cudaGetSymbolAddress((void**)&pW1h, g_W1t_h);
    cudaGetSymbolAddress((void**)&pW1l, g_W1t_l);
    cudaGetSymbolAddress((void**)&pW2h, g_W2t_h);
    cudaGetSymbolAddress((void**)&pW2l, g_W2t_l);

    static cudaStream_t sB = nullptr, sC = nullptr;
    static cudaEvent_t evF = nullptr, evZ = nullptr, evCSR = nullptr, evDeg = nullptr;
    if (!sB) {
        cudaStreamCreateWithFlags(&sB, cudaStreamNonBlocking);
        cudaStreamCreateWithFlags(&sC, cudaStreamNonBlocking);
        cudaEventCreateWithFlags(&evF,   cudaEventDisableTiming);
        cudaEventCreateWithFlags(&evZ,   cudaEventDisableTiming);
        cudaEventCreateWithFlags(&evCSR, cudaEventDisableTiming);
        cudaEventCreateWithFlags(&evDeg, cudaEventDisableTiming);
        cudaFuncSetAttribute(k_gemm_mma<16, FIN, FIN, 512, NN, false>,
                             cudaFuncAttributeMaxDynamicSharedMemorySize, GEMM_SMEM);
        cudaFuncSetAttribute(k_gemm_mma<3, HH, HH, 128, 2 * NN, true>,
                             cudaFuncAttributeMaxDynamicSharedMemorySize, GEMM_SMEM);
    }

    const int GN  = (NN + 255) / 256;
    const int GE  = (EE + 255) / 256;
    const int GW  = (NN * 32 + 255) / 256;           // warp-per-node
    const int GS1 = (NN * 24 + 383) / 384;           // spmm1 groups
    const int GT1 = (NN + 127) / 128;
    const int GT2 = (2 * NN + 127) / 128;

    // fork point
    cudaEventRecord(evF, 0);
    cudaStreamWaitEvent(sB, evF, 0);
    cudaStreamWaitEvent(sC, evF, 0);

    // (1) main: weight prep (GEMM1's only dependency)
    k_wprep<<<(HH * 512 + 255) / 256, 256>>>(W1, W2, Wm, bm);

    // side B: zero degs -> count_in -> 3-phase scan -> scatter
    k_zero<<<GN, 256, 0, sB>>>();
    cudaEventRecord(evZ, sB);
    k_count_in<<<GE, 256, 0, sB>>>(dst);
    k_scan_a<<<NB, 256, 0, sB>>>();
    k_scan_b<<<1, 256, 0, sB>>>();
    k_scan_c<<<NB, 256, 0, sB>>>();
    k_scatter<<<GE, 256, 0, sB>>>(src, dst);
    cudaEventRecord(evCSR, sB);

    // main: GEMM1, no degree dependency
    k_gemm_mma<16, FIN, FIN, 512, NN, false>
        <<<GT1, 256, GEMM_SMEM>>>(x, pW1h, pW1l, pYp);

    // side C: count_out, hidden under GEMM1
    cudaStreamWaitEvent(sC, evZ, 0);
    k_count_out<<<GE, 256, 0, sC>>>(src);
    cudaEventRecord(evDeg, sC);

    // main: scale both views (needs deg_out + Yplain)
    cudaStreamWaitEvent(0, evDeg, 0);
    k_permscale2<<<GW, 256>>>(perm);

    // main: spmm1 -> GEMM2 -> spmm2
    cudaStreamWaitEvent(0, evCSR, 0);
    k_spmm1<<<GS1, 384>>>(b1, a1);
    k_gemm_mma<3, HH, HH, 128, 2 * NN, true>
        <<<GT2, 256, GEMM_SMEM>>>(pB0h, pW2h, pW2l, pB2h);
    k_spmm2<<<GW, 256>>>(b2, a2, out);
}

// round 10
// speedup vs baseline: 2.4210x; 1.0443x over previous
#include <cuda_runtime.h>
#include <cuda_bf16.h>
#include <cuda_fp16.h>
#include <cstdint>

#define NN 50000
#define EE 800000
#define FIN 500
#define HH 96
#define NB 196        // scan blocks: ceil(NN/256)

// ---------------- scratch (device globals; no allocation allowed) ----------
__device__ int    g_deg_out[NN];
__device__ int    g_deg_in[NN];
__device__ int    g_iperm[NN];
__device__ int    g_off[NN + 1];
__device__ int    g_cur[NN];
__device__ int    g_bsum[NB];
__device__ int    g_boff[NB];
__device__ int    g_csr[EE];             // src per CSR slot
__device__ __half g_Y01[NN * 2 * HH];    // [norm_out*Y | norm_out*Y[perm]] per node
__device__ __half g_B0h[2 * NN * HH];    // layer-1 out, row n=2i+v, fp16
__device__ __half g_B2h[2 * NN * HH];    // B0 @ W2, row n=2i+v, fp16
__device__ float  g_wmsum[HH];
__device__ float  g_bmsum;
// transposed (n-major, k-contiguous), zero-padded, bf16 hi/lo weight copies
__device__ __nv_bfloat16 g_W1t_h[HH * 512];
__device__ __nv_bfloat16 g_W1t_l[HH * 512];
__device__ __nv_bfloat16 g_W2t_h[HH * 128];
__device__ __nv_bfloat16 g_W2t_l[HH * 128];

// ---------------- helpers ----------------------------------------------------
__device__ __forceinline__ uint32_t cvt2bf(float x, float y) {   // lo=x, hi=y
    uint32_t r;
    asm("cvt.rn.bf16x2.f32 %0, %1, %2;" : "=r"(r) : "f"(y), "f"(x));
    return r;
}

__device__ __forceinline__ void split_pair(float x, float y,
                                           uint32_t& hp, uint32_t& lp) {
    hp = cvt2bf(x, y);
    float fx = __uint_as_float(hp << 16);
    float fy = __uint_as_float(hp & 0xffff0000u);
    lp = cvt2bf(x - fx, y - fy);
}

__device__ __forceinline__ void mma16816(float* c, uint32_t a0, uint32_t a1,
                                         uint32_t a2, uint32_t a3,
                                         uint32_t b0, uint32_t b1) {
    asm volatile(
        "mma.sync.aligned.m16n8k16.row.col.f32.bf16.bf16.f32 "
        "{%0,%1,%2,%3}, {%4,%5,%6,%7}, {%8,%9}, {%0,%1,%2,%3};"
        : "+f"(c[0]), "+f"(c[1]), "+f"(c[2]), "+f"(c[3])
        : "r"(a0), "r"(a1), "r"(a2), "r"(a3), "r"(b0), "r"(b1));
}

// 256-thread block inclusive scan
__device__ __forceinline__ int block_scan256(int v, int tid) {
    int lane = tid & 31, wid = tid >> 5;
    int inc = v;
    #pragma unroll
    for (int o = 1; o < 32; o <<= 1) {
        int u = __shfl_up_sync(0xffffffffu, inc, o);
        if (lane >= o) inc += u;
    }
    __shared__ int ws[8];
    if (lane == 31) ws[wid] = inc;
    __syncthreads();
    if (wid == 0) {
        int w = (lane < 8) ? ws[lane] : 0;
        #pragma unroll
        for (int o = 1; o < 8; o <<= 1) {
            int u = __shfl_up_sync(0xffffffffu, w, o);
            if (lane >= o) w += u;
        }
        if (lane < 8) ws[lane] = w;
    }
    __syncthreads();
    return inc + (wid ? ws[wid - 1] : 0);
}

// ---------------- setup kernels --------------------------------------------
__global__ void k_zero() {
    int i = blockIdx.x * blockDim.x + threadIdx.x;
    if (i < NN) { g_deg_out[i] = 0; g_deg_in[i] = 0; }
}

__global__ void k_iperm(const int* __restrict__ perm) {
    int i = blockIdx.x * blockDim.x + threadIdx.x;
    if (i < NN) g_iperm[perm[i]] = i;
}

__global__ void k_count_out(const int* __restrict__ src) {
    int e = blockIdx.x * blockDim.x + threadIdx.x;
    if (e < EE) atomicAdd(&g_deg_out[src[e]], 1);
}

__global__ void k_count_in(const int* __restrict__ dst) {
    int e = blockIdx.x * blockDim.x + threadIdx.x;
    if (e < EE) atomicAdd(&g_deg_in[dst[e]], 1);
}

__global__ void k_scan_a() {
    int tid = threadIdx.x;
    int i = blockIdx.x * 256 + tid;
    int v = (i < NN) ? g_deg_in[i] : 0;
    #pragma unroll
    for (int o = 16; o; o >>= 1) v += __shfl_down_sync(0xffffffffu, v, o);
    __shared__ int ws[8];
    if ((tid & 31) == 0) ws[tid >> 5] = v;
    __syncthreads();
    if (tid < 8) {
        int s = ws[tid];
        #pragma unroll
        for (int o = 4; o; o >>= 1) s += __shfl_down_sync(0xffu, s, o);
        if (tid == 0) g_bsum[blockIdx.x] = s;
    }
}

__global__ void k_scan_b() {
    int tid = threadIdx.x;
    int v = (tid < NB) ? g_bsum[tid] : 0;
    int inc = block_scan256(v, tid);
    if (tid < NB) g_boff[tid] = inc - v;
    if (tid == 0) g_off[NN] = EE;
}

__global__ void k_scan_c() {
    int tid = threadIdx.x;
    int i = blockIdx.x * 256 + tid;
    int v = (i < NN) ? g_deg_in[i] : 0;
    int inc = block_scan256(v, tid);
    int run = g_boff[blockIdx.x] + inc - v;
    if (i < NN) { g_off[i] = run; g_cur[i] = run; }
}

__global__ void k_scatter(const int* __restrict__ src, const int* __restrict__ dst) {
    int e = blockIdx.x * blockDim.x + threadIdx.x;
    if (e < EE) {
        int p = atomicAdd(&g_cur[dst[e]], 1);
        g_csr[p] = src[e];
    }
}

__global__ void k_wprep(const float* __restrict__ W1, const float* __restrict__ W2,
                        const float* __restrict__ Wm, const float* __restrict__ bm) {
    int idx = blockIdx.x * blockDim.x + threadIdx.x;
    if (idx < HH * 512) {
        int j = idx >> 9, k = idx & 511;
        float v = (k < FIN) ? W1[k * HH + j] : 0.f;
        __nv_bfloat16 h = __float2bfloat16_rn(v);
        g_W1t_h[idx] = h;
        g_W1t_l[idx] = __float2bfloat16_rn(v - __bfloat162float(h));
    }
    if (idx < HH * 128) {
        int j = idx >> 7, k = idx & 127;
        float v = (k < HH) ? W2[k * HH + j] : 0.f;
        __nv_bfloat16 h = __float2bfloat16_rn(v);
        g_W2t_h[idx] = h;
        g_W2t_l[idx] = __float2bfloat16_rn(v - __bfloat162float(h));
    }
    if (blockIdx.x == 0 && threadIdx.x < HH) {
        int k = threadIdx.x;
        float s = 0.f;
        for (int j = 0; j < HH; j++) s += Wm[k * HH + j];
        g_wmsum[k] = s;
        if (k == 0) {
            float sb = 0.f;
            for (int j = 0; j < HH; j++) sb += bm[j];
            g_bmsum = sb;
        }
    }
}

// ---------------- tensor-core GEMM via mma.sync, double-buffered ------------
// CTA: 128 rows x 96 cols, 8 warps as 4(m) x 2(n); warp = 2 m16 bands x 6 n8.
// EPI1: write Y01 both views (view0 at row, view1 at iperm[row], each scaled).
#define AB_U32 2176              // 128*17
#define BB_U32 1632              // 96*17
#define GEMM_SMEM ((4 * AB_U32 + 4 * BB_U32) * 4)   // 60928 bytes

template <int KCHUNKS, int KREAL, int LDA, int WLD, int NROWS, bool HALF_IN, bool EPI1>
__global__ void __launch_bounds__(256, 2)
k_gemm_mma(const void* __restrict__ Ain,
           const __nv_bfloat16* __restrict__ Wh,
           const __nv_bfloat16* __restrict__ Wl,
           __half* __restrict__ C) {
    extern __shared__ uint32_t dyn[];
    uint32_t* const AhB[2] = { dyn,               dyn + 2 * AB_U32 };
    uint32_t* const AlB[2] = { dyn + AB_U32,      dyn + 3 * AB_U32 };
    uint32_t* const bbase  = dyn + 4 * AB_U32;
    uint32_t* const BhB[2] = { bbase,             bbase + 2 * BB_U32 };
    uint32_t* const BlB[2] = { bbase + BB_U32,    bbase + 3 * BB_U32 };

    int tid = threadIdx.x, wid = tid >> 5, lane = tid & 31;
    int mw = wid >> 1, nw = wid & 1;
    int r0 = blockIdx.x * 128;

    float acc[2][6][4];
    #pragma unroll
    for (int b = 0; b < 2; b++)
        #pragma unroll
        for (int t = 0; t < 6; t++)
            #pragma unroll
            for (int j = 0; j < 4; j++) acc[b][t][j] = 0.f;

    const int qr = lane >> 2, qc = lane & 3;

    float4   va4[4];     // fp32 path: 4 x float4 per chunk
    float2   va2[8];     // fp16 path
    uint32_t vbh[6], vbl[6];

    #define LOAD_CHUNK(cc)                                                     \
    {                                                                          \
        int kbase = (cc) * 32;                                                 \
        if (HALF_IN) {                                                         \
            int kvp = (KREAL - kbase) >> 1;                                    \
            if (kvp > 16) kvp = 16;                                            \
            _Pragma("unroll")                                                  \
            for (int it = 0; it < 8; it++) {                                   \
                int idx = tid + it * 256;                                      \
                int r = idx >> 4, kp = idx & 15;                               \
                int gr = r0 + r;                                               \
                float2 v = make_float2(0.f, 0.f);                              \
                if (gr < NROWS && kp < kvp) {                                  \
                    __half2 h2 = *(const __half2*)((const __half*)Ain +        \
                                   (size_t)gr * LDA + kbase + 2 * kp);         \
                    v = __half22float2(h2);                                    \
                }                                                              \
                va2[it] = v;                                                   \
            }                                                                  \
        } else {                                                               \
            int kvq = (KREAL - kbase + 3) >> 2;                                \
            if (kvq > 8) kvq = 8;                                              \
            _Pragma("unroll")                                                  \
            for (int it = 0; it < 4; it++) {                                   \
                int idx = tid + it * 256;                                      \
                int r = idx >> 3, q = idx & 7;                                 \
                int gr = r0 + r;                                               \
                float4 v = make_float4(0.f, 0.f, 0.f, 0.f);                    \
                if (gr < NROWS && q < kvq)                                     \
                    v = *(const float4*)((const float*)Ain +                   \
                            (size_t)gr * LDA + kbase + 4 * q);                 \
                va4[it] = v;                                                   \
            }                                                                  \
        }                                                                      \
        _Pragma("unroll")                                                      \
        for (int it = 0; it < 6; it++) {                                       \
            int idx = tid + it * 256;                                          \
            int n = idx >> 4, kp = idx & 15;                                   \
            vbh[it] = *(const uint32_t*)(Wh + (size_t)n * WLD + kbase + 2 * kp);\
            vbl[it] = *(const uint32_t*)(Wl + (size_t)n * WLD + kbase + 2 * kp);\
        }                                                                      \
    }

    #define STORE_CHUNK(buf)                                                   \
    {                                                                          \
        if (HALF_IN) {                                                         \
            _Pragma("unroll")                                                  \
            for (int it = 0; it < 8; it++) {                                   \
                int idx = tid + it * 256;                                      \
                int r = idx >> 4, kp = idx & 15;                               \
                uint32_t hp, lp;                                               \
                split_pair(va2[it].x, va2[it].y, hp, lp);                      \
                AhB[buf][r * 17 + kp] = hp;                                    \
                AlB[buf][r * 17 + kp] = lp;                                    \
            }                                                                  \
        } else {                                                               \
            _Pragma("unroll")                                                  \
            for (int it = 0; it < 4; it++) {                                   \
                int idx = tid + it * 256;                                      \
                int r = idx >> 3, q = idx & 7;                                 \
                float4 v = va4[it];                                            \
                uint32_t h0, l0, h1, l1;                                       \
                split_pair(v.x, v.y, h0, l0);                                  \
                split_pair(v.z, v.w, h1, l1);                                  \
                AhB[buf][r * 17 + 2 * q]     = h0;                             \
                AhB[buf][r * 17 + 2 * q + 1] = h1;                             \
                AlB[buf][r * 17 + 2 * q]     = l0;                             \
                AlB[buf][r * 17 + 2 * q + 1] = l1;                             \
            }                                                                  \
        }                                                                      \
        _Pragma("unroll")                                                      \
        for (int it = 0; it < 6; it++) {                                       \
            int idx = tid + it * 256;                                          \
            int n = idx >> 4, kp = idx & 15;                                   \
            BhB[buf][n * 17 + kp] = vbh[it];                                   \
            BlB[buf][n * 17 + kp] = vbl[it];                                   \
        }                                                                      \
    }

    LOAD_CHUNK(0);
    STORE_CHUNK(0);
    __syncthreads();

    for (int c = 0; c < KCHUNKS; c++) {
        if (c + 1 < KCHUNKS) LOAD_CHUNK(c + 1);

        const uint32_t* sAh = AhB[c & 1];
        const uint32_t* sAl = AlB[c & 1];
        const uint32_t* sBh = BhB[c & 1];
        const uint32_t* sBl = BlB[c & 1];

        #pragma unroll
        for (int s = 0; s < 2; s++) {
            int kq = s * 8 + qc;
            uint32_t bh[6][2], bl[6][2];
            #pragma unroll
            for (int t = 0; t < 6; t++) {
                int bc = nw * 48 + t * 8 + qr;
                bh[t][0] = sBh[bc * 17 + kq]; bh[t][1] = sBh[bc * 17 + kq + 4];
                bl[t][0] = sBl[bc * 17 + kq]; bl[t][1] = sBl[bc * 17 + kq + 4];
            }
            #pragma unroll
            for (int b = 0; b < 2; b++) {
                int ar = mw * 32 + b * 16 + qr;
                uint32_t ah0 = sAh[ar * 17 + kq],       ah1 = sAh[(ar + 8) * 17 + kq];
                uint32_t ah2 = sAh[ar * 17 + kq + 4],   ah3 = sAh[(ar + 8) * 17 + kq + 4];
                uint32_t al0 = sAl[ar * 17 + kq],       al1 = sAl[(ar + 8) * 17 + kq];
                uint32_t al2 = sAl[ar * 17 + kq + 4],   al3 = sAl[(ar + 8) * 17 + kq + 4];
                #pragma unroll
                for (int t = 0; t < 6; t++) {
                    mma16816(acc[b][t], ah0, ah1, ah2, ah3, bh[t][0], bh[t][1]);
                    mma16816(acc[b][t], ah0, ah1, ah2, ah3, bl[t][0], bl[t][1]);
                    mma16816(acc[b][t], al0, al1, al2, al3, bh[t][0], bh[t][1]);
                }
            }
        }

        if (c + 1 < KCHUNKS) {
            STORE_CHUNK((c + 1) & 1);
            __syncthreads();
        }
    }

    if (EPI1) {
        #pragma unroll
        for (int b = 0; b < 2; b++)
            #pragma unroll
            for (int h = 0; h < 2; h++) {
                int row = r0 + mw * 32 + b * 16 + qr + h * 8;
                if (row < NROWS) {
                    float no1 = rsqrtf((float)max(g_deg_out[row], 1));
                    int   n2  = g_iperm[row];
                    float no2 = rsqrtf((float)max(g_deg_out[n2], 1));
                    #pragma unroll
                    for (int t = 0; t < 6; t++) {
                        int col = nw * 48 + t * 8 + 2 * qc;
                        float vx = acc[b][t][2 * h], vy = acc[b][t][2 * h + 1];
                        *(__half2*)(g_Y01 + (size_t)row * (2 * HH) + col) =
                            __floats2half2_rn(no1 * vx, no1 * vy);
                        *(__half2*)(g_Y01 + (size_t)n2 * (2 * HH) + HH + col) =
                            __floats2half2_rn(no2 * vx, no2 * vy);
                    }
                }
            }
    } else {
        #pragma unroll
        for (int b = 0; b < 2; b++)
            #pragma unroll
            for (int t = 0; t < 6; t++) {
                int col = nw * 48 + t * 8 + 2 * qc;
                #pragma unroll
                for (int h = 0; h < 2; h++) {
                    int row = r0 + mw * 32 + b * 16 + qr + h * 8;
                    if (row < NROWS)
                        *(__half2*)(C + (size_t)row * HH + col) =
                            __floats2half2_rn(acc[b][t][2 * h], acc[b][t][2 * h + 1]);
                }
            }
    }
    #undef LOAD_CHUNK
    #undef STORE_CHUNK
}

// ---------------- SpMM gather core: 4x unrolled, 16B/lane -------------------
__device__ __forceinline__ void spmm_gather(const __half* __restrict__ base,
                                            size_t loff, int b, int e,
                                            float* acc) {
    #pragma unroll
    for (int t = 0; t < 8; t++) acc[t] = 0.f;
    auto addv = [&](uint4 v) {
        __half2* h2 = (__half2*)&v;
        #pragma unroll
        for (int t = 0; t < 4; t++) {
            float2 f = __half22float2(h2[t]);
            acc[2 * t]     += f.x;
            acc[2 * t + 1] += f.y;
        }
    };
    int p = b;
    for (; p + 4 <= e; p += 4) {
        int s0 = g_csr[p], s1 = g_csr[p + 1], s2 = g_csr[p + 2], s3 = g_csr[p + 3];
        uint4 v0 = *(const uint4*)(base + (size_t)s0 * (2 * HH) + loff);
        uint4 v1 = *(const uint4*)(base + (size_t)s1 * (2 * HH) + loff);
        uint4 v2 = *(const uint4*)(base + (size_t)s2 * (2 * HH) + loff);
        uint4 v3 = *(const uint4*)(base + (size_t)s3 * (2 * HH) + loff);
        addv(v0); addv(v1); addv(v2); addv(v3);
    }
    for (; p < e; p++)
        addv(*(const uint4*)(base + (size_t)g_csr[p] * (2 * HH) + loff));
}

// ---------------- fused SpMM layer 1: thread = (node, 24-chunk) -------------
__global__ void __launch_bounds__(384)
k_spmm1(const float* __restrict__ b1, const float* __restrict__ a1) {
    __shared__ float sb1[HH], sa1[HH];
    for (int j = threadIdx.x; j < HH; j += blockDim.x) {
        sb1[j] = b1[j];
        sa1[j] = a1[j];
    }
    __syncthreads();

    int nl = threadIdx.x / 24, c = threadIdx.x - nl * 24;
    int n = blockIdx.x * 16 + nl;
    if (n >= NN) return;
    int view = c / 12, chunk = c - view * 12;
    int b = g_off[n], e = g_off[n + 1];

    float acc[8];
    spmm_gather(g_Y01, (size_t)view * HH + chunk * 8, b, e, acc);

    float nin  = rsqrtf((float)max(g_deg_in[n], 1));
    float nout = rsqrtf((float)max(g_deg_out[n], 1));
    uint4 o;
    __half2* oh = (__half2*)&o;
    #pragma unroll
    for (int q = 0; q < 4; q++) {
        float r[2];
        #pragma unroll
        for (int u = 0; u < 2; u++) {
            int j = chunk * 8 + 2 * q + u;
            float h = fmaf(acc[2 * q + u], nin, sb1[j]);
            h = (h >= 0.f) ? h : sa1[j] * h;
            r[u] = nout * h;
        }
        oh[q] = __floats2half2_rn(r[0], r[1]);
    }
    *(uint4*)(g_B0h + ((size_t)(2 * n + view)) * HH + chunk * 8) = o;
}

// ---------------- fused SpMM layer 2 + readout: 24-thread groups ------------
__global__ void __launch_bounds__(384)
k_spmm2(const float* __restrict__ b2, const float* __restrict__ a2,
        float* __restrict__ out) {
    __shared__ float sb2[HH], sa2[HH], swm[HH], sp[384];
    for (int j = threadIdx.x; j < HH; j += blockDim.x) {
        sb2[j] = b2[j];
        sa2[j] = a2[j];
        swm[j] = g_wmsum[j];
    }
    __syncthreads();

    int nl = threadIdx.x / 24, c = threadIdx.x - nl * 24;
    int n = blockIdx.x * 16 + nl;
    int view = c / 12, chunk = c - view * 12;

    float part = 0.f;
    if (n < NN) {
        int b = g_off[n], e = g_off[n + 1];
        float acc[8];
        spmm_gather(g_B2h, (size_t)view * HH + chunk * 8, b, e, acc);
        float nin = rsqrtf((float)max(g_deg_in[n], 1));
        #pragma unroll
        for (int t = 0; t < 8; t++) {
            int j = chunk * 8 + t;
            float h = fmaf(acc[t], nin, sb2[j]);
            h = (h >= 0.f) ? h : sa2[j] * h;
            part = fmaf(h, swm[j], part);
        }
    }
    sp[threadIdx.x] = part;
    __syncthreads();

    if (threadIdx.x < 32) {
        int nl2 = threadIdx.x >> 1, vw = threadIdx.x & 1;
        int n2 = blockIdx.x * 16 + nl2;
        if (n2 < NN) {
            float s = g_bmsum;
            #pragma unroll
            for (int k = 0; k < 12; k++) s += sp[nl2 * 24 + vw * 12 + k];
            out[(size_t)vw * NN + n2] = s;
        }
    }
}

// ---------------- launch ----------------------------------------------------
extern "C" void kernel_launch(void* const* d_in, const int* in_sizes, int n_in,
                              void* d_out, int out_size) {
    const float* x    = (const float*)d_in[0];
    const int*   src  = (const int*)  d_in[1];
    const int*   dst  = (const int*)  d_in[2];
    const int*   perm = (const int*)  d_in[3];
    const float* W1   = (const float*)d_in[4];
    const float* b1   = (const float*)d_in[5];
    const float* a1   = (const float*)d_in[6];
    const float* W2   = (const float*)d_in[7];
    const float* b2   = (const float*)d_in[8];
    const float* a2   = (const float*)d_in[9];
    const float* Wm   = (const float*)d_in[10];
    const float* bm   = (const float*)d_in[11];
    float* out = (float*)d_out;

    __half *pB0h, *pB2h;
    __nv_bfloat16 *pW1h, *pW1l, *pW2h, *pW2l;
    cudaGetSymbolAddress((void**)&pB0h, g_B0h);
    cudaGetSymbolAddress((void**)&pB2h, g_B2h);
    cudaGetSymbolAddress((void**)&pW1h, g_W1t_h);
    cudaGetSymbolAddress((void**)&pW1l, g_W1t_l);
    cudaGetSymbolAddress((void**)&pW2h, g_W2t_h);
    cudaGetSymbolAddress((void**)&pW2l, g_W2t_l);

    static cudaStream_t sB = nullptr, sC = nullptr;
    static cudaEvent_t evF = nullptr, evZ = nullptr, evCSR = nullptr, evDeg = nullptr;
    if (!sB) {
        cudaStreamCreateWithFlags(&sB, cudaStreamNonBlocking);
        cudaStreamCreateWithFlags(&sC, cudaStreamNonBlocking);
        cudaEventCreateWithFlags(&evF,   cudaEventDisableTiming);
        cudaEventCreateWithFlags(&evZ,   cudaEventDisableTiming);
        cudaEventCreateWithFlags(&evCSR, cudaEventDisableTiming);
        cudaEventCreateWithFlags(&evDeg, cudaEventDisableTiming);
        cudaFuncSetAttribute(k_gemm_mma<16, FIN, FIN, 512, NN, false, true>,
                             cudaFuncAttributeMaxDynamicSharedMemorySize, GEMM_SMEM);
        cudaFuncSetAttribute(k_gemm_mma<3, HH, HH, 128, 2 * NN, true, false>,
                             cudaFuncAttributeMaxDynamicSharedMemorySize, GEMM_SMEM);
    }

    const int GN  = (NN + 255) / 256;
    const int GE  = (EE + 255) / 256;
    const int GS  = (NN + 15) / 16;                  // 24-thread-group kernels
    const int GT1 = (NN + 127) / 128;
    const int GT2 = (2 * NN + 127) / 128;

    // fork point
    cudaEventRecord(evF, 0);
    cudaStreamWaitEvent(sB, evF, 0);
    cudaStreamWaitEvent(sC, evF, 0);

    // main: weight prep
    k_wprep<<<(HH * 512 + 255) / 256, 256>>>(W1, W2, Wm, bm);

    // side B: zero degs -> count_in -> 3-phase scan -> scatter
    k_zero<<<GN, 256, 0, sB>>>();
    cudaEventRecord(evZ, sB);
    k_count_in<<<GE, 256, 0, sB>>>(dst);
    k_scan_a<<<NB, 256, 0, sB>>>();
    k_scan_b<<<1, 256, 0, sB>>>();
    k_scan_c<<<NB, 256, 0, sB>>>();
    k_scatter<<<GE, 256, 0, sB>>>(src, dst);
    cudaEventRecord(evCSR, sB);

    // side C: iperm, then count_out (after zero)
    k_iperm<<<GN, 256, 0, sC>>>(perm);
    cudaStreamWaitEvent(sC, evZ, 0);
    k_count_out<<<GE, 256, 0, sC>>>(src);
    cudaEventRecord(evDeg, sC);

    // main: GEMM1 (needs weights + deg_out + iperm); epilogue writes Y01 both views
    cudaStreamWaitEvent(0, evDeg, 0);
    k_gemm_mma<16, FIN, FIN, 512, NN, false, true>
        <<<GT1, 256, GEMM_SMEM>>>(x, pW1h, pW1l, pB0h /*unused*/);

    // main: spmm1 -> GEMM2 -> spmm2
    cudaStreamWaitEvent(0, evCSR, 0);
    k_spmm1<<<GS, 384>>>(b1, a1);
    k_gemm_mma<3, HH, HH, 128, 2 * NN, true, false>
        <<<GT2, 256, GEMM_SMEM>>>(pB0h, pW2h, pW2l, pB2h);
    k_spmm2<<<GS, 384>>>(b2, a2, out);
}